// round 10
// baseline (speedup 1.0000x reference)
#include <cuda_runtime.h>
#include <math.h>

#define CIN    512
#define COUT   512
#define NB     8
#define HW     4096          // 64*64
#define Mtot   32768         // NB*HW
#define KKtot  4608          // CIN*9
#define NANCH  36864         // HW*9
#define PRE_NMS  2000
#define POST_NMS 300
#define DEPTH  16
#define NSTEP  288           // 9 taps * 32 c-blocks of depth 16
#define PADW   66
#define PADA   4356          // 66*66
#define CBSTRIDE 69696       // 16 channels * 4356 floats per c-block in g_xpad

#define OFF_LOCS   0
#define OFF_SCORES 1179648
#define OFF_ROIS   1769472
#define OFF_IDX    1779072

// ---------------- scratch (device globals; no allocs allowed) ----------------
__device__ float g_h[COUT * Mtot];                       // conv1 output, [cout][m]
__device__ float g_wt[COUT * KKtot];                     // weights re-laid out [k][rs*512+c]
__device__ float g_xpad[NB * CIN * PADA];                // zero-padded input, [n][c][66][66]
__device__ float g_boxes[NB * NANCH * 4];
__device__ float g_fg[NB * NANCH];
__device__ float g_topbox[NB * PRE_NMS * 4];
__device__ unsigned long long g_mask[NB * PRE_NMS * 32]; // suppression bitmask

// packed f32x2 FMA: both halves are independent IEEE fp32 FMAs (bitwise == fmaf per lane)
__device__ __forceinline__ void ffma2(unsigned long long& d, unsigned long long a, unsigned long long b) {
    asm("fma.rn.f32x2 %0, %1, %2, %0;" : "+l"(d) : "l"(a), "l"(b));
}
__device__ __forceinline__ float f2lo(unsigned long long v) { return __uint_as_float((unsigned)(v & 0xFFFFFFFFull)); }
__device__ __forceinline__ float f2hi(unsigned long long v) { return __uint_as_float((unsigned)(v >> 32)); }

// base anchors (ymin,xmin,ymax,xmax), order: ratio-major, scale-minor (matches reference)
__constant__ float c_ba[9][4] = {
    { -37.254833995939045f,  -82.50966799187809f,   53.254833995939045f,  98.50966799187809f },
    { -82.50966799187809f,  -173.01933598375618f,   98.50966799187809f,  189.01933598375618f },
    { -173.01933598375618f, -354.03867196751236f,  189.01933598375618f,  370.03867196751236f },
    { -56.f,  -56.f,   72.f,   72.f },
    { -120.f, -120.f,  136.f,  136.f },
    { -248.f, -248.f,  264.f,  264.f },
    { -82.50966799187809f,   -37.254833995939045f,  98.50966799187809f,   53.254833995939045f },
    { -173.01933598375618f,  -82.50966799187809f,  189.01933598375618f,   98.50966799187809f },
    { -354.03867196751236f, -173.01933598375618f,  370.03867196751236f,  189.01933598375618f },
};

// ---------------- weight transpose: OIHW [k][c*9+rs] -> [k][rs*512+c] ----------------
__global__ void wtrans_kernel(const float* __restrict__ W) {
    int gid = blockIdx.x * blockDim.x + threadIdx.x;
    if (gid >= COUT * KKtot) return;
    int k  = gid / KKtot;
    int t  = gid - k * KKtot;
    int rs = t >> 9;          // 0..8
    int c  = t & 511;
    g_wt[gid] = W[(size_t)k * KKtot + c * 9 + rs];
}

// ---------------- input halo padding: X[n][c][64][64] -> g_xpad[n][c][66][66] ----------------
__global__ void xpad_kernel(const float* __restrict__ X) {
    int plane = blockIdx.y;                      // 0..4095  (n*512 + c)
    int e = blockIdx.x * blockDim.x + threadIdx.x;
    if (e >= PADA) return;
    int iy = e / PADW, ix = e - iy * PADW;
    float v = 0.f;
    if (iy >= 1 && iy <= 64 && ix >= 1 && ix <= 64)
        v = X[((size_t)plane << 12) + ((iy - 1) << 6) + (ix - 1)];
    g_xpad[(size_t)plane * PADA + e] = v;
}

// ---------------- conv1: 3x3 512->512 + bias + ReLU (implicit im2col SGEMM, FFMA2) ----------------
// Round-6 configuration (proven best; at ~95% of FFMA2 bank-limited roofline). Do not touch.
__global__ __launch_bounds__(256, 2)
void conv1_kernel(const float* __restrict__ Bias) {
    __shared__ float2 As2[2][DEPTH][128];   // weights duplicated {a,a}   32KB
    __shared__ float  Bs[2][DEPTH][128];    //                            16KB

    int bk  = blockIdx.x;           // 0..3    (out-channel tile)
    int bm  = blockIdx.y;           // 0..255  (m tile)
    int tid = threadIdx.x;
    int tx  = tid & 15, ty = tid >> 4;

    unsigned long long acc2[8][4];
#pragma unroll
    for (int i = 0; i < 8; i++)
#pragma unroll
        for (int p = 0; p < 4; p++) acc2[i][p] = 0ull;

    int a_i  = tid >> 1;            // 0..127
    int a_k8 = (tid & 1) * 8;       // 0 or 8
    const float* wrow = g_wt + (size_t)(bk * 128 + a_i) * KKtot + a_k8;
    int m0 = bm * 128;

    // per-thread fixed gather bases (element e: idx = tid + 256e, e=0..7)
    int e_kk[8], e_j[8];
    int base_e[8];
#pragma unroll
    for (int e = 0; e < 8; e++) {
        int idx = tid + 256 * e;
        e_kk[e] = idx >> 7;         // 0..15
        e_j[e]  = idx & 127;
        int m   = m0 + e_j[e];
        int n   = m >> 12;
        int p   = m & 4095;
        int yy  = p >> 6, xx = p & 63;
        base_e[e] = (n * CIN + e_kk[e]) * PADA + (yy + 1) * PADW + (xx + 1);
    }

    float4 av0, av1;
    float  bv[8];

    // prefetch stage 0 (rs=0 => dy=-1,dx=-1 => delta = -67; cb=0)
    av0 = *reinterpret_cast<const float4*>(wrow);
    av1 = *reinterpret_cast<const float4*>(wrow + 4);
#pragma unroll
    for (int e = 0; e < 8; e++) bv[e] = g_xpad[base_e[e] - 67];

#pragma unroll
    for (int q = 0; q < 4; q++) {
        float a = (&av0.x)[q];
        As2[0][a_k8 + q][a_i] = make_float2(a, a);
    }
#pragma unroll
    for (int q = 0; q < 4; q++) {
        float a = (&av1.x)[q];
        As2[0][a_k8 + 4 + q][a_i] = make_float2(a, a);
    }
#pragma unroll
    for (int e = 0; e < 8; e++) Bs[0][e_kk[e]][e_j[e]] = bv[e];
    __syncthreads();

    for (int st = 0; st < NSTEP; st++) {
        int cur = st & 1;
        int stn = st + 1;
        bool havenext = stn < NSTEP;

        // prefetch next stage into registers (hidden under the FMA loop)
        if (havenext) {
            av0 = *reinterpret_cast<const float4*>(wrow + stn * DEPTH);
            av1 = *reinterpret_cast<const float4*>(wrow + stn * DEPTH + 4);
            int rs = stn >> 5, cb = stn & 31;
            int r  = rs / 3, s = rs - 3 * r;
            int c_off = (r - 1) * PADW + (s - 1) + cb * CBSTRIDE;
#pragma unroll
            for (int e = 0; e < 8; e++) bv[e] = g_xpad[base_e[e] + c_off];
        }

        // FMA on current buffer
#pragma unroll
        for (int kk = 0; kk < DEPTH; kk++) {
            ulonglong2 aq0 = *reinterpret_cast<const ulonglong2*>(&As2[cur][kk][ty * 8 + 0]);
            ulonglong2 aq1 = *reinterpret_cast<const ulonglong2*>(&As2[cur][kk][ty * 8 + 2]);
            ulonglong2 aq2 = *reinterpret_cast<const ulonglong2*>(&As2[cur][kk][ty * 8 + 4]);
            ulonglong2 aq3 = *reinterpret_cast<const ulonglong2*>(&As2[cur][kk][ty * 8 + 6]);
            ulonglong2 bq0 = *reinterpret_cast<const ulonglong2*>(&Bs[cur][kk][tx * 4]);
            ulonglong2 bq1 = *reinterpret_cast<const ulonglong2*>(&Bs[cur][kk][tx * 4 + 64]);
            unsigned long long a2[8] = { aq0.x, aq0.y, aq1.x, aq1.y, aq2.x, aq2.y, aq3.x, aq3.y };
            unsigned long long b2[4] = { bq0.x, bq0.y, bq1.x, bq1.y };
#pragma unroll
            for (int i = 0; i < 8; i++)
#pragma unroll
                for (int p = 0; p < 4; p++)
                    ffma2(acc2[i][p], a2[i], b2[p]);
        }

        // store prefetched stage into the other buffer
        if (havenext) {
            int nb = stn & 1;
#pragma unroll
            for (int q = 0; q < 4; q++) {
                float a = (&av0.x)[q];
                As2[nb][a_k8 + q][a_i] = make_float2(a, a);
            }
#pragma unroll
            for (int q = 0; q < 4; q++) {
                float a = (&av1.x)[q];
                As2[nb][a_k8 + 4 + q][a_i] = make_float2(a, a);
            }
#pragma unroll
            for (int e = 0; e < 8; e++) Bs[nb][e_kk[e]][e_j[e]] = bv[e];
        }
        __syncthreads();
    }

    // epilogue: bias + ReLU, write to g_h[k][m] as float4
#pragma unroll
    for (int i = 0; i < 8; i++) {
        int ko = bk * 128 + ty * 8 + i;
        float bias = Bias[ko];
#pragma unroll
        for (int h = 0; h < 2; h++) {
            float4 v;
            v.x = fmaxf(f2lo(acc2[i][h * 2 + 0]) + bias, 0.f);
            v.y = fmaxf(f2hi(acc2[i][h * 2 + 0]) + bias, 0.f);
            v.z = fmaxf(f2lo(acc2[i][h * 2 + 1]) + bias, 0.f);
            v.w = fmaxf(f2hi(acc2[i][h * 2 + 1]) + bias, 0.f);
            *reinterpret_cast<float4*>(&g_h[(size_t)ko * Mtot + m0 + tx * 4 + h * 64]) = v;
        }
    }
}

// ---------------- 1x1 convs: 54 channels, FFMA2, 4 cols/thread (LDS:FFMA2 = 1:2) ----------------
// 256 blocks x 256 threads. ty 0..7 owns 7 channels (gch = ty*7+ch; 54,55 dummies).
// tx owns 4 columns {4tx..4tx+3} = two even/odd-adjacent f32x2 pairs (same pairing as before).
// Per cc: one LDG.128 + 7 LDS.64 + 14 FFMA2. Chains strict ascending-c -> bitwise identical.
__global__ __launch_bounds__(256)
void conv1x1_kernel(const float* __restrict__ LW, const float* __restrict__ LB,
                    const float* __restrict__ SW, const float* __restrict__ SB,
                    float* __restrict__ out) {
    __shared__ float2 ws2[56][64];       // duplicated weights {w,w}, 28KB
    int tid = threadIdx.x;
    int tx  = tid & 31, ty = tid >> 5;   // ty 0..7
    int m0  = blockIdx.x * 128;          // 128 columns per block

    unsigned long long acc2[7][2];
#pragma unroll
    for (int ch = 0; ch < 7; ch++) { acc2[ch][0] = 0ull; acc2[ch][1] = 0ull; }

    const float* hbase = &g_h[m0 + tx * 4];

    for (int c0 = 0; c0 < CIN; c0 += 64) {
        __syncthreads();
        for (int t = tid; t < 56 * 64; t += 256) {
            int ch = t >> 6, cc = t & 63;
            float w = 0.f;
            if (ch < 36)      w = LW[ch * CIN + c0 + cc];
            else if (ch < 54) w = SW[(ch - 36) * CIN + c0 + cc];
            ws2[ch][cc] = make_float2(w, w);
        }
        __syncthreads();
#pragma unroll 1
        for (int cg = 0; cg < 64; cg += 2) {
            ulonglong2 hq0 = *reinterpret_cast<const ulonglong2*>(
                hbase + (size_t)(c0 + cg) * Mtot);
            ulonglong2 hq1 = *reinterpret_cast<const ulonglong2*>(
                hbase + (size_t)(c0 + cg + 1) * Mtot);
#pragma unroll
            for (int ch = 0; ch < 7; ch++) {
                unsigned long long w0 = *reinterpret_cast<const unsigned long long*>(
                    &ws2[ty * 7 + ch][cg]);
                ffma2(acc2[ch][0], w0, hq0.x);
                ffma2(acc2[ch][1], w0, hq0.y);
            }
#pragma unroll
            for (int ch = 0; ch < 7; ch++) {
                unsigned long long w1 = *reinterpret_cast<const unsigned long long*>(
                    &ws2[ty * 7 + ch][cg + 1]);
                ffma2(acc2[ch][0], w1, hq1.x);
                ffma2(acc2[ch][1], w1, hq1.y);
            }
        }
    }

#pragma unroll
    for (int ch = 0; ch < 7; ch++) {
        int gch = ty * 7 + ch;
        if (gch >= 54) continue;
#pragma unroll
        for (int e = 0; e < 4; e++) {
            int m = m0 + tx * 4 + e;
            int n = m >> 12, p = m & 4095;
            unsigned long long a = acc2[ch][e >> 1];
            float v = (e & 1) ? f2hi(a) : f2lo(a);
            if (gch < 36) {
                int an = gch >> 2, j = gch & 3;
                out[OFF_LOCS + ((size_t)n * NANCH + p * 9 + an) * 4 + j] = v + LB[gch];
            } else {
                int sch = gch - 36;
                int an = sch >> 1, j = sch & 1;
                out[OFF_SCORES + ((size_t)n * NANCH + p * 9 + an) * 2 + j] = v + SB[sch];
            }
        }
    }
}

// ---------------- decode + clip + size filter ----------------
__global__ void decode_kernel(const float* __restrict__ out,
                              const int* __restrict__ ihp, const int* __restrict__ iwp) {
    int gid = blockIdx.x * blockDim.x + threadIdx.x;
    if (gid >= NB * NANCH) return;
    int i = gid % NANCH;
    int a = i % 9;
    int p = i / 9;
    float sy = (float)((p >> 6) * 16);
    float sx = (float)((p & 63) * 16);
    float ay0 = sy + c_ba[a][0], ax0 = sx + c_ba[a][1];
    float ay1 = sy + c_ba[a][2], ax1 = sx + c_ba[a][3];
    float ah = ay1 - ay0, aw = ax1 - ax0;
    float acy = ay0 + 0.5f * ah, acx = ax0 + 0.5f * aw;

    float4 l = *(const float4*)&out[OFF_LOCS + (size_t)gid * 4];
    float cy = l.x * ah + acy;
    float cx = l.y * aw + acx;
    float hh = expf(l.z) * ah;
    float ww = expf(l.w) * aw;

    int vih = *ihp, viw = *iwp;
    float Hc = (vih > 0 && vih < 65536) ? (float)vih : __int_as_float(vih);
    float Wc = (viw > 0 && viw < 65536) ? (float)viw : __int_as_float(viw);

    float y0 = fminf(fmaxf(cy - 0.5f * hh, 0.f), Hc);
    float x0 = fminf(fmaxf(cx - 0.5f * ww, 0.f), Wc);
    float y1 = fminf(fmaxf(cy + 0.5f * hh, 0.f), Hc);
    float x1 = fminf(fmaxf(cx + 0.5f * ww, 0.f), Wc);

    *(float4*)&g_boxes[(size_t)gid * 4] = make_float4(y0, x0, y1, x1);
    float sc = out[OFF_SCORES + (size_t)gid * 2 + 1];
    g_fg[gid] = ((y1 - y0) >= 16.f && (x1 - x0) >= 16.f) ? sc : -INFINITY;
}

// ---------------- per-image exact top-2000 (radix select + bitonic sort) ----------------
__device__ __forceinline__ unsigned int fkey(float f) {
    unsigned int b = __float_as_uint(f);
    return (b & 0x80000000u) ? ~b : (b | 0x80000000u);
}

__global__ __launch_bounds__(1024)
void topk_kernel() {
    int n = blockIdx.x;
    const float* fg = g_fg + (size_t)n * NANCH;
    __shared__ unsigned int hist[256];
    __shared__ unsigned int sPref;
    __shared__ int sK, sCnt;
    __shared__ unsigned long long keys[4096];
    int tid = threadIdx.x;

    unsigned int pref = 0; int k = PRE_NMS;
    for (int pass = 0; pass < 4; pass++) {
        int shift = 24 - pass * 8;
        if (tid < 256) hist[tid] = 0u;
        __syncthreads();
        unsigned int mhi = pass ? (0xFFFFFFFFu << (shift + 8)) : 0u;
        for (int i = tid; i < NANCH; i += 1024) {
            unsigned int u = fkey(fg[i]);
            if ((u & mhi) == pref) atomicAdd(&hist[(u >> shift) & 255u], 1u);
        }
        __syncthreads();
        if (tid == 0) {
            int acc = 0, b = 255;
            for (; b > 0; b--) {
                if (acc + (int)hist[b] >= k) break;
                acc += (int)hist[b];
            }
            sPref = pref | ((unsigned)b << shift);
            sK = k - acc;
        }
        __syncthreads();
        pref = sPref; k = sK;
        __syncthreads();
    }
    unsigned int T = pref;
    if (tid == 0) sCnt = 0;
    __syncthreads();
    for (int i = tid; i < NANCH; i += 1024) {
        unsigned int u = fkey(fg[i]);
        if (u >= T) {
            int pos = atomicAdd(&sCnt, 1);
            if (pos < 4096)
                keys[pos] = ((unsigned long long)u << 32) | (unsigned)(0xFFFFFFFFu - (unsigned)i);
        }
    }
    __syncthreads();
    int cnt = sCnt < 4096 ? sCnt : 4096;
    for (int i = cnt + tid; i < 4096; i += 1024) keys[i] = 0ull;

    // bitonic sort, descending (ties: smaller original index first via ~i in low bits)
    for (int size = 2; size <= 4096; size <<= 1) {
        for (int stride = size >> 1; stride > 0; stride >>= 1) {
            __syncthreads();
            for (int t = tid; t < 2048; t += 1024) {
                int i = ((t & ~(stride - 1)) << 1) | (t & (stride - 1));
                int j = i | stride;
                unsigned long long ki = keys[i], kj = keys[j];
                bool descBlock = (i & size) == 0;
                if (descBlock ? (ki < kj) : (ki > kj)) { keys[i] = kj; keys[j] = ki; }
            }
        }
    }
    __syncthreads();

    for (int t = tid; t < PRE_NMS; t += 1024) {
        int idx = (int)(0xFFFFFFFFu - (unsigned int)(keys[t] & 0xFFFFFFFFull));
        float4 b4 = *(const float4*)&g_boxes[((size_t)n * NANCH + idx) * 4];
        *(float4*)&g_topbox[((size_t)n * PRE_NMS + t) * 4] = b4;
    }
}

// ---------------- pairwise IoU suppression bitmask ----------------
__global__ __launch_bounds__(64)
void iou_mask_kernel() {
    int n = blockIdx.z, rb = blockIdx.y, cb = blockIdx.x;
    int t = threadIdx.x;

    // whole block strictly lower-triangle (every col <= every row) -> all-zero mask words
    if (cb < rb) {
        int row = rb * 64 + t;
        if (row < PRE_NMS) g_mask[((size_t)n * PRE_NMS + row) * 32 + cb] = 0ull;
        return;
    }

    __shared__ float4 cbox[64];
    int col0 = cb * 64;
    cbox[t] = (col0 + t < PRE_NMS)
                  ? *(const float4*)&g_topbox[((size_t)n * PRE_NMS + col0 + t) * 4]
                  : make_float4(0, 0, 0, 0);
    __syncthreads();

    int row = rb * 64 + t;
    if (row >= PRE_NMS) return;
    float4 r4 = *(const float4*)&g_topbox[((size_t)n * PRE_NMS + row) * 4];
    float areaR = (r4.z - r4.x) * (r4.w - r4.y);
    unsigned long long bits = 0ull;
    int cmax = min(64, PRE_NMS - col0);
    for (int c = 0; c < cmax; c++) {
        int col = col0 + c;
        if (col <= row) continue;
        float4 c4 = cbox[c];
        float areaC = (c4.z - c4.x) * (c4.w - c4.y);
        float tly = fmaxf(r4.x, c4.x), tlx = fmaxf(r4.y, c4.y);
        float bry = fminf(r4.z, c4.z), brx = fminf(r4.w, c4.w);
        float ih = fmaxf(bry - tly, 0.f), iw = fmaxf(brx - tlx, 0.f);
        float inter = ih * iw;
        float iou = inter / (areaR + areaC - inter + 1e-9f);
        if (iou > 0.7f) bits |= (1ull << c);
    }
    g_mask[((size_t)n * PRE_NMS + row) * 32 + cb] = bits;
}

// ---------------- serial NMS scan (register rem + shfl + deep prefetch) ----------------
#define NMS_PF 25            // prefetch depth; 2000 = 25 * 80
__global__ __launch_bounds__(32)
void nms_scan_kernel(float* __restrict__ out) {
    int n = blockIdx.x;
    int lane = threadIdx.x;
    const unsigned long long* M = g_mask + (size_t)n * PRE_NMS * 32;

    __shared__ int keep[POST_NMS];
    unsigned long long rem = 0ull;     // this lane's 64-column suppression chunk
    int cnt = 0;                        // replicated across lanes

    unsigned long long pre[NMS_PF];
#pragma unroll
    for (int u = 0; u < NMS_PF; u++) pre[u] = M[(size_t)u * 32 + lane];

    for (int base = 0; base < PRE_NMS; base += NMS_PF) {
#pragma unroll
        for (int u = 0; u < NMS_PF; u++) {
            int i = base + u;
            unsigned long long mrow = pre[u];
            int nx = i + NMS_PF;
            if (nx < PRE_NMS) pre[u] = M[(size_t)nx * 32 + lane];
            unsigned long long word = __shfl_sync(0xFFFFFFFFu, rem, i >> 6);
            bool sup = (word >> (i & 63)) & 1ull;
            if (!sup) {
                rem |= mrow;
                if (lane == 0 && cnt < POST_NMS) keep[cnt] = i;
                cnt++;
            }
        }
    }
    __syncwarp();
    int c = cnt < POST_NMS ? cnt : POST_NMS;

    for (int k = lane; k < POST_NMS; k += 32) {
        float4 b = make_float4(0, 0, 0, 0);
        if (k < c) b = *(const float4*)&g_topbox[((size_t)n * PRE_NMS + keep[k]) * 4];
        *(float4*)&out[OFF_ROIS + ((size_t)n * POST_NMS + k) * 4] = b;
        out[OFF_IDX + (size_t)n * POST_NMS + k] = (float)n;
    }
}

// ---------------- launch ----------------
extern "C" void kernel_launch(void* const* d_in, const int* in_sizes, int n_in,
                              void* d_out, int out_size) {
    const float* x   = (const float*)d_in[0];
    const float* c1w = (const float*)d_in[1];
    const float* c1b = (const float*)d_in[2];
    const float* sw  = (const float*)d_in[3];
    const float* sb  = (const float*)d_in[4];
    const float* lw  = (const float*)d_in[5];
    const float* lb  = (const float*)d_in[6];
    const int*   ih  = (const int*)d_in[7];
    const int*   iw  = (const int*)d_in[8];
    float* out = (float*)d_out;

    wtrans_kernel<<<(COUT * KKtot + 255) / 256, 256>>>(c1w);
    xpad_kernel<<<dim3((PADA + 255) / 256, NB * CIN), 256>>>(x);
    conv1_kernel<<<dim3(4, 256), 256>>>(c1b);
    conv1x1_kernel<<<256, 256>>>(lw, lb, sw, sb, out);
    decode_kernel<<<(NB * NANCH + 255) / 256, 256>>>(out, ih, iw);
    topk_kernel<<<NB, 1024>>>();
    iou_mask_kernel<<<dim3(32, 32, NB), 64>>>();
    nms_scan_kernel<<<NB, 32>>>(out);
}

// round 11
// speedup vs baseline: 1.0027x; 1.0027x over previous
#include <cuda_runtime.h>
#include <math.h>

#define CIN    512
#define COUT   512
#define NB     8
#define HW     4096          // 64*64
#define Mtot   32768         // NB*HW
#define KKtot  4608          // CIN*9
#define NANCH  36864         // HW*9
#define PRE_NMS  2000
#define POST_NMS 300
#define DEPTH  32
#define NSTEP  144           // 9 taps * 16 c-blocks of depth 32
#define PADW   66
#define PADA   4356          // 66*66
#define CBSTRIDE 139392      // 32 channels * 4356 floats per c-block in g_xpad
#define CONV1_SMEM (96 * 1024)   // As2 64KB + Bs 32KB; 2x96 fits -> 2 CTAs/SM

#define OFF_LOCS   0
#define OFF_SCORES 1179648
#define OFF_ROIS   1769472
#define OFF_IDX    1779072

// ---------------- scratch (device globals; no allocs allowed) ----------------
__device__ float g_h[COUT * Mtot];                       // conv1 output, [cout][m]
__device__ float g_wt[COUT * KKtot];                     // weights re-laid out [k][rs*512+c]
__device__ float g_xpad[NB * CIN * PADA];                // zero-padded input, [n][c][66][66]
__device__ float g_boxes[NB * NANCH * 4];
__device__ float g_fg[NB * NANCH];
__device__ float g_topbox[NB * PRE_NMS * 4];
__device__ unsigned long long g_mask[NB * PRE_NMS * 32]; // suppression bitmask

// packed f32x2 FMA: both halves are independent IEEE fp32 FMAs (bitwise == fmaf per lane)
__device__ __forceinline__ void ffma2(unsigned long long& d, unsigned long long a, unsigned long long b) {
    asm("fma.rn.f32x2 %0, %1, %2, %0;" : "+l"(d) : "l"(a), "l"(b));
}
__device__ __forceinline__ float f2lo(unsigned long long v) { return __uint_as_float((unsigned)(v & 0xFFFFFFFFull)); }
__device__ __forceinline__ float f2hi(unsigned long long v) { return __uint_as_float((unsigned)(v >> 32)); }

// base anchors (ymin,xmin,ymax,xmax), order: ratio-major, scale-minor (matches reference)
__constant__ float c_ba[9][4] = {
    { -37.254833995939045f,  -82.50966799187809f,   53.254833995939045f,  98.50966799187809f },
    { -82.50966799187809f,  -173.01933598375618f,   98.50966799187809f,  189.01933598375618f },
    { -173.01933598375618f, -354.03867196751236f,  189.01933598375618f,  370.03867196751236f },
    { -56.f,  -56.f,   72.f,   72.f },
    { -120.f, -120.f,  136.f,  136.f },
    { -248.f, -248.f,  264.f,  264.f },
    { -82.50966799187809f,   -37.254833995939045f,  98.50966799187809f,   53.254833995939045f },
    { -173.01933598375618f,  -82.50966799187809f,  189.01933598375618f,   98.50966799187809f },
    { -354.03867196751236f, -173.01933598375618f,  370.03867196751236f,  189.01933598375618f },
};

// ---------------- weight transpose: OIHW [k][c*9+rs] -> [k][rs*512+c] ----------------
__global__ void wtrans_kernel(const float* __restrict__ W) {
    int gid = blockIdx.x * blockDim.x + threadIdx.x;
    if (gid >= COUT * KKtot) return;
    int k  = gid / KKtot;
    int t  = gid - k * KKtot;
    int rs = t >> 9;          // 0..8
    int c  = t & 511;
    g_wt[gid] = W[(size_t)k * KKtot + c * 9 + rs];
}

// ---------------- input halo padding: X[n][c][64][64] -> g_xpad[n][c][66][66] ----------------
__global__ void xpad_kernel(const float* __restrict__ X) {
    int plane = blockIdx.y;                      // 0..4095  (n*512 + c)
    int e = blockIdx.x * blockDim.x + threadIdx.x;
    if (e >= PADA) return;
    int iy = e / PADW, ix = e - iy * PADW;
    float v = 0.f;
    if (iy >= 1 && iy <= 64 && ix >= 1 && ix <= 64)
        v = X[((size_t)plane << 12) + ((iy - 1) << 6) + (ix - 1)];
    g_xpad[(size_t)plane * PADA + e] = v;
}

// ---------------- conv1: 3x3 512->512 + bias + ReLU (implicit im2col SGEMM, FFMA2) ----------------
// K-order: rs outer (r asc, s asc), c inner asc, depth-32 stages. One chain per output,
// identical global accumulation order to all prior passing rounds.
// Thread owns 8 rows x 8 cols; cols = {4tx..4tx+3} and {4tx+64..4tx+67}.
// 96KB dynamic smem -> exactly 2 CTAs/SM (16 warps) with half the stages/barriers of DEPTH16.
__global__ __launch_bounds__(256, 2)
void conv1_kernel(const float* __restrict__ Bias) {
    extern __shared__ char smem_raw[];
    // As2: [2][DEPTH][128] float2 = 64KB ; Bs: [2][DEPTH][128] float = 32KB
    float2 (*As2)[DEPTH][128] = reinterpret_cast<float2 (*)[DEPTH][128]>(smem_raw);
    float  (*Bs)[DEPTH][128]  = reinterpret_cast<float (*)[DEPTH][128]>(smem_raw + 65536);

    int bk  = blockIdx.x;           // 0..3    (out-channel tile)
    int bm  = blockIdx.y;           // 0..255  (m tile)
    int tid = threadIdx.x;
    int tx  = tid & 15, ty = tid >> 4;

    unsigned long long acc2[8][4];
#pragma unroll
    for (int i = 0; i < 8; i++)
#pragma unroll
        for (int p = 0; p < 4; p++) acc2[i][p] = 0ull;

    int a_i   = tid >> 1;           // 0..127
    int a_k16 = (tid & 1) * 16;     // 0 or 16
    const float* wrow = g_wt + (size_t)(bk * 128 + a_i) * KKtot + a_k16;
    int m0 = bm * 128;

    // per-thread fixed gather base (element e: idx = tid + 256e, e=0..15)
    // kk = (tid>>7) + 2e, j = tid & 127 (same spatial column for all e)
    int jcol = tid & 127;
    int kk0  = tid >> 7;            // 0 or 1
    int base0;
    {
        int m  = m0 + jcol;
        int n  = m >> 12;
        int p  = m & 4095;
        int yy = p >> 6, xx = p & 63;
        base0 = (n * CIN + kk0) * PADA + (yy + 1) * PADW + (xx + 1);
    }

    float4 av[4];
    float  bv[16];

    // prefetch stage 0 (rs=0 => dy=-1,dx=-1 => delta = -67; cb=0)
#pragma unroll
    for (int q = 0; q < 4; q++)
        av[q] = *reinterpret_cast<const float4*>(wrow + q * 4);
#pragma unroll
    for (int e = 0; e < 16; e++)
        bv[e] = g_xpad[base0 + e * (2 * PADA) - 67];

#pragma unroll
    for (int q = 0; q < 16; q++) {
        float a = (&av[q >> 2].x)[q & 3];
        As2[0][a_k16 + q][a_i] = make_float2(a, a);
    }
#pragma unroll
    for (int e = 0; e < 16; e++) Bs[0][kk0 + 2 * e][jcol] = bv[e];
    __syncthreads();

    for (int st = 0; st < NSTEP; st++) {
        int cur = st & 1;
        int stn = st + 1;
        bool havenext = stn < NSTEP;

        // prefetch next stage into registers (hidden under the FMA loop)
        if (havenext) {
#pragma unroll
            for (int q = 0; q < 4; q++)
                av[q] = *reinterpret_cast<const float4*>(wrow + stn * DEPTH + q * 4);
            int rs = stn >> 4, cb = stn & 15;
            int r  = rs / 3, s = rs - 3 * r;
            int c_off = (r - 1) * PADW + (s - 1) + cb * CBSTRIDE;
#pragma unroll
            for (int e = 0; e < 16; e++)
                bv[e] = g_xpad[base0 + e * (2 * PADA) + c_off];
        }

        // FMA on current buffer
#pragma unroll
        for (int kk = 0; kk < DEPTH; kk++) {
            ulonglong2 aq0 = *reinterpret_cast<const ulonglong2*>(&As2[cur][kk][ty * 8 + 0]);
            ulonglong2 aq1 = *reinterpret_cast<const ulonglong2*>(&As2[cur][kk][ty * 8 + 2]);
            ulonglong2 aq2 = *reinterpret_cast<const ulonglong2*>(&As2[cur][kk][ty * 8 + 4]);
            ulonglong2 aq3 = *reinterpret_cast<const ulonglong2*>(&As2[cur][kk][ty * 8 + 6]);
            ulonglong2 bq0 = *reinterpret_cast<const ulonglong2*>(&Bs[cur][kk][tx * 4]);
            ulonglong2 bq1 = *reinterpret_cast<const ulonglong2*>(&Bs[cur][kk][tx * 4 + 64]);
            unsigned long long a2[8] = { aq0.x, aq0.y, aq1.x, aq1.y, aq2.x, aq2.y, aq3.x, aq3.y };
            unsigned long long b2[4] = { bq0.x, bq0.y, bq1.x, bq1.y };
#pragma unroll
            for (int i = 0; i < 8; i++)
#pragma unroll
                for (int p = 0; p < 4; p++)
                    ffma2(acc2[i][p], a2[i], b2[p]);
        }

        // store prefetched stage into the other buffer
        if (havenext) {
            int nb = stn & 1;
#pragma unroll
            for (int q = 0; q < 16; q++) {
                float a = (&av[q >> 2].x)[q & 3];
                As2[nb][a_k16 + q][a_i] = make_float2(a, a);
            }
#pragma unroll
            for (int e = 0; e < 16; e++) Bs[nb][kk0 + 2 * e][jcol] = bv[e];
        }
        __syncthreads();
    }

    // epilogue: bias + ReLU, write to g_h[k][m] as float4
#pragma unroll
    for (int i = 0; i < 8; i++) {
        int ko = bk * 128 + ty * 8 + i;
        float bias = Bias[ko];
#pragma unroll
        for (int h = 0; h < 2; h++) {
            float4 v;
            v.x = fmaxf(f2lo(acc2[i][h * 2 + 0]) + bias, 0.f);
            v.y = fmaxf(f2hi(acc2[i][h * 2 + 0]) + bias, 0.f);
            v.z = fmaxf(f2lo(acc2[i][h * 2 + 1]) + bias, 0.f);
            v.w = fmaxf(f2hi(acc2[i][h * 2 + 1]) + bias, 0.f);
            *reinterpret_cast<float4*>(&g_h[(size_t)ko * Mtot + m0 + tx * 4 + h * 64]) = v;
        }
    }
}

// ---------------- 1x1 convs: 54 channels (36 loc + 18 score), FFMA2, latency-hidden ----------------
// Round-6 proven version. 512 blocks x 256 threads. ty 0..7 owns 7 channels; tx owns 2 adjacent
// columns (even/odd pair -> same f32x2 pairing, chains ascending-c).
__global__ __launch_bounds__(256)
void conv1x1_kernel(const float* __restrict__ LW, const float* __restrict__ LB,
                    const float* __restrict__ SW, const float* __restrict__ SB,
                    float* __restrict__ out) {
    __shared__ float2 ws2[56][64];       // duplicated weights {w,w}, 28KB
    int tid = threadIdx.x;
    int tx  = tid & 31, ty = tid >> 5;   // ty 0..7
    int m0  = blockIdx.x * 64;           // 64 columns per block

    unsigned long long acc2[7];
#pragma unroll
    for (int ch = 0; ch < 7; ch++) acc2[ch] = 0ull;

    for (int c0 = 0; c0 < CIN; c0 += 64) {
        __syncthreads();
        for (int t = tid; t < 56 * 64; t += 256) {
            int ch = t >> 6, cc = t & 63;
            float w = 0.f;
            if (ch < 36)      w = LW[ch * CIN + c0 + cc];
            else if (ch < 54) w = SW[(ch - 36) * CIN + c0 + cc];
            ws2[ch][cc] = make_float2(w, w);
        }
        __syncthreads();
        for (int cc = 0; cc < 64; cc++) {
            unsigned long long hv = *reinterpret_cast<const unsigned long long*>(
                &g_h[(size_t)(c0 + cc) * Mtot + m0 + tx * 2]);
#pragma unroll
            for (int ch = 0; ch < 7; ch++) {
                unsigned long long w2 = *reinterpret_cast<const unsigned long long*>(
                    &ws2[ty * 7 + ch][cc]);
                ffma2(acc2[ch], w2, hv);
            }
        }
    }

#pragma unroll
    for (int ch = 0; ch < 7; ch++) {
        int gch = ty * 7 + ch;
        if (gch >= 54) continue;
#pragma unroll
        for (int e = 0; e < 2; e++) {
            int m = m0 + tx * 2 + e;
            int n = m >> 12, p = m & 4095;
            float v = e ? f2hi(acc2[ch]) : f2lo(acc2[ch]);
            if (gch < 36) {
                int an = gch >> 2, j = gch & 3;
                out[OFF_LOCS + ((size_t)n * NANCH + p * 9 + an) * 4 + j] = v + LB[gch];
            } else {
                int sch = gch - 36;
                int an = sch >> 1, j = sch & 1;
                out[OFF_SCORES + ((size_t)n * NANCH + p * 9 + an) * 2 + j] = v + SB[sch];
            }
        }
    }
}

// ---------------- decode + clip + size filter ----------------
__global__ void decode_kernel(const float* __restrict__ out,
                              const int* __restrict__ ihp, const int* __restrict__ iwp) {
    int gid = blockIdx.x * blockDim.x + threadIdx.x;
    if (gid >= NB * NANCH) return;
    int i = gid % NANCH;
    int a = i % 9;
    int p = i / 9;
    float sy = (float)((p >> 6) * 16);
    float sx = (float)((p & 63) * 16);
    float ay0 = sy + c_ba[a][0], ax0 = sx + c_ba[a][1];
    float ay1 = sy + c_ba[a][2], ax1 = sx + c_ba[a][3];
    float ah = ay1 - ay0, aw = ax1 - ax0;
    float acy = ay0 + 0.5f * ah, acx = ax0 + 0.5f * aw;

    float4 l = *(const float4*)&out[OFF_LOCS + (size_t)gid * 4];
    float cy = l.x * ah + acy;
    float cx = l.y * aw + acx;
    float hh = expf(l.z) * ah;
    float ww = expf(l.w) * aw;

    int vih = *ihp, viw = *iwp;
    float Hc = (vih > 0 && vih < 65536) ? (float)vih : __int_as_float(vih);
    float Wc = (viw > 0 && viw < 65536) ? (float)viw : __int_as_float(viw);

    float y0 = fminf(fmaxf(cy - 0.5f * hh, 0.f), Hc);
    float x0 = fminf(fmaxf(cx - 0.5f * ww, 0.f), Wc);
    float y1 = fminf(fmaxf(cy + 0.5f * hh, 0.f), Hc);
    float x1 = fminf(fmaxf(cx + 0.5f * ww, 0.f), Wc);

    *(float4*)&g_boxes[(size_t)gid * 4] = make_float4(y0, x0, y1, x1);
    float sc = out[OFF_SCORES + (size_t)gid * 2 + 1];
    g_fg[gid] = ((y1 - y0) >= 16.f && (x1 - x0) >= 16.f) ? sc : -INFINITY;
}

// ---------------- per-image exact top-2000 (radix select + bitonic sort) ----------------
__device__ __forceinline__ unsigned int fkey(float f) {
    unsigned int b = __float_as_uint(f);
    return (b & 0x80000000u) ? ~b : (b | 0x80000000u);
}

__global__ __launch_bounds__(1024)
void topk_kernel() {
    int n = blockIdx.x;
    const float* fg = g_fg + (size_t)n * NANCH;
    __shared__ unsigned int hist[256];
    __shared__ unsigned int sPref;
    __shared__ int sK, sCnt;
    __shared__ unsigned long long keys[4096];
    int tid = threadIdx.x;

    unsigned int pref = 0; int k = PRE_NMS;
    for (int pass = 0; pass < 4; pass++) {
        int shift = 24 - pass * 8;
        if (tid < 256) hist[tid] = 0u;
        __syncthreads();
        unsigned int mhi = pass ? (0xFFFFFFFFu << (shift + 8)) : 0u;
        for (int i = tid; i < NANCH; i += 1024) {
            unsigned int u = fkey(fg[i]);
            if ((u & mhi) == pref) atomicAdd(&hist[(u >> shift) & 255u], 1u);
        }
        __syncthreads();
        if (tid == 0) {
            int acc = 0, b = 255;
            for (; b > 0; b--) {
                if (acc + (int)hist[b] >= k) break;
                acc += (int)hist[b];
            }
            sPref = pref | ((unsigned)b << shift);
            sK = k - acc;
        }
        __syncthreads();
        pref = sPref; k = sK;
        __syncthreads();
    }
    unsigned int T = pref;
    if (tid == 0) sCnt = 0;
    __syncthreads();
    for (int i = tid; i < NANCH; i += 1024) {
        unsigned int u = fkey(fg[i]);
        if (u >= T) {
            int pos = atomicAdd(&sCnt, 1);
            if (pos < 4096)
                keys[pos] = ((unsigned long long)u << 32) | (unsigned)(0xFFFFFFFFu - (unsigned)i);
        }
    }
    __syncthreads();
    int cnt = sCnt < 4096 ? sCnt : 4096;
    for (int i = cnt + tid; i < 4096; i += 1024) keys[i] = 0ull;

    // bitonic sort, descending (ties: smaller original index first via ~i in low bits)
    for (int size = 2; size <= 4096; size <<= 1) {
        for (int stride = size >> 1; stride > 0; stride >>= 1) {
            __syncthreads();
            for (int t = tid; t < 2048; t += 1024) {
                int i = ((t & ~(stride - 1)) << 1) | (t & (stride - 1));
                int j = i | stride;
                unsigned long long ki = keys[i], kj = keys[j];
                bool descBlock = (i & size) == 0;
                if (descBlock ? (ki < kj) : (ki > kj)) { keys[i] = kj; keys[j] = ki; }
            }
        }
    }
    __syncthreads();

    for (int t = tid; t < PRE_NMS; t += 1024) {
        int idx = (int)(0xFFFFFFFFu - (unsigned int)(keys[t] & 0xFFFFFFFFull));
        float4 b4 = *(const float4*)&g_boxes[((size_t)n * NANCH + idx) * 4];
        *(float4*)&g_topbox[((size_t)n * PRE_NMS + t) * 4] = b4;
    }
}

// ---------------- pairwise IoU suppression bitmask ----------------
__global__ __launch_bounds__(64)
void iou_mask_kernel() {
    int n = blockIdx.z, rb = blockIdx.y, cb = blockIdx.x;
    int t = threadIdx.x;

    // whole block strictly lower-triangle (every col <= every row) -> all-zero mask words
    if (cb < rb) {
        int row = rb * 64 + t;
        if (row < PRE_NMS) g_mask[((size_t)n * PRE_NMS + row) * 32 + cb] = 0ull;
        return;
    }

    __shared__ float4 cbox[64];
    int col0 = cb * 64;
    cbox[t] = (col0 + t < PRE_NMS)
                  ? *(const float4*)&g_topbox[((size_t)n * PRE_NMS + col0 + t) * 4]
                  : make_float4(0, 0, 0, 0);
    __syncthreads();

    int row = rb * 64 + t;
    if (row >= PRE_NMS) return;
    float4 r4 = *(const float4*)&g_topbox[((size_t)n * PRE_NMS + row) * 4];
    float areaR = (r4.z - r4.x) * (r4.w - r4.y);
    unsigned long long bits = 0ull;
    int cmax = min(64, PRE_NMS - col0);
    for (int c = 0; c < cmax; c++) {
        int col = col0 + c;
        if (col <= row) continue;
        float4 c4 = cbox[c];
        float areaC = (c4.z - c4.x) * (c4.w - c4.y);
        float tly = fmaxf(r4.x, c4.x), tlx = fmaxf(r4.y, c4.y);
        float bry = fminf(r4.z, c4.z), brx = fminf(r4.w, c4.w);
        float ih = fmaxf(bry - tly, 0.f), iw = fmaxf(brx - tlx, 0.f);
        float inter = ih * iw;
        float iou = inter / (areaR + areaC - inter + 1e-9f);
        if (iou > 0.7f) bits |= (1ull << c);
    }
    g_mask[((size_t)n * PRE_NMS + row) * 32 + cb] = bits;
}

// ---------------- serial NMS scan (register rem + shfl + deep prefetch) ----------------
#define NMS_PF 25            // prefetch depth; 2000 = 25 * 80
__global__ __launch_bounds__(32)
void nms_scan_kernel(float* __restrict__ out) {
    int n = blockIdx.x;
    int lane = threadIdx.x;
    const unsigned long long* M = g_mask + (size_t)n * PRE_NMS * 32;

    __shared__ int keep[POST_NMS];
    unsigned long long rem = 0ull;     // this lane's 64-column suppression chunk
    int cnt = 0;                        // replicated across lanes

    unsigned long long pre[NMS_PF];
#pragma unroll
    for (int u = 0; u < NMS_PF; u++) pre[u] = M[(size_t)u * 32 + lane];

    for (int base = 0; base < PRE_NMS; base += NMS_PF) {
#pragma unroll
        for (int u = 0; u < NMS_PF; u++) {
            int i = base + u;
            unsigned long long mrow = pre[u];
            int nx = i + NMS_PF;
            if (nx < PRE_NMS) pre[u] = M[(size_t)nx * 32 + lane];
            unsigned long long word = __shfl_sync(0xFFFFFFFFu, rem, i >> 6);
            bool sup = (word >> (i & 63)) & 1ull;
            if (!sup) {
                rem |= mrow;
                if (lane == 0 && cnt < POST_NMS) keep[cnt] = i;
                cnt++;
            }
        }
    }
    __syncwarp();
    int c = cnt < POST_NMS ? cnt : POST_NMS;

    for (int k = lane; k < POST_NMS; k += 32) {
        float4 b = make_float4(0, 0, 0, 0);
        if (k < c) b = *(const float4*)&g_topbox[((size_t)n * PRE_NMS + keep[k]) * 4];
        *(float4*)&out[OFF_ROIS + ((size_t)n * POST_NMS + k) * 4] = b;
        out[OFF_IDX + (size_t)n * POST_NMS + k] = (float)n;
    }
}

// ---------------- launch ----------------
extern "C" void kernel_launch(void* const* d_in, const int* in_sizes, int n_in,
                              void* d_out, int out_size) {
    const float* x   = (const float*)d_in[0];
    const float* c1w = (const float*)d_in[1];
    const float* c1b = (const float*)d_in[2];
    const float* sw  = (const float*)d_in[3];
    const float* sb  = (const float*)d_in[4];
    const float* lw  = (const float*)d_in[5];
    const float* lb  = (const float*)d_in[6];
    const int*   ih  = (const int*)d_in[7];
    const int*   iw  = (const int*)d_in[8];
    float* out = (float*)d_out;

    cudaFuncSetAttribute(conv1_kernel, cudaFuncAttributeMaxDynamicSharedMemorySize, CONV1_SMEM);

    wtrans_kernel<<<(COUT * KKtot + 255) / 256, 256>>>(c1w);
    xpad_kernel<<<dim3((PADA + 255) / 256, NB * CIN), 256>>>(x);
    conv1_kernel<<<dim3(4, 256), 256, CONV1_SMEM>>>(c1b);
    conv1x1_kernel<<<512, 256>>>(lw, lb, sw, sb, out);
    decode_kernel<<<(NB * NANCH + 255) / 256, 256>>>(out, ih, iw);
    topk_kernel<<<NB, 1024>>>();
    iou_mask_kernel<<<dim3(32, 32, NB), 64>>>();
    nms_scan_kernel<<<NB, 32>>>(out);
}

// round 15
// speedup vs baseline: 1.0069x; 1.0042x over previous
#include <cuda_runtime.h>
#include <stdint.h>
#include <math.h>

#define CIN    512
#define COUT   512
#define NB     8
#define HW     4096          // 64*64
#define Mtot   32768         // NB*HW
#define KKtot  4608          // CIN*9
#define NANCH  36864         // HW*9
#define PRE_NMS  2000
#define POST_NMS 300
#define DEPTH  16
#define NSTEP  288           // 9 taps * 32 c-blocks of depth 16
#define PADW   66
#define PADA   4356          // 66*66
#define CBSTRIDE 69696       // 16 channels * 4356 floats per c-block in g_xpad

#define OFF_LOCS   0
#define OFF_SCORES 1179648
#define OFF_ROIS   1769472
#define OFF_IDX    1779072

// ---------------- scratch (device globals; no allocs allowed) ----------------
__device__ float g_h[COUT * Mtot];                       // conv1 output, [cout][m]
__device__ float g_wt[COUT * KKtot];                     // weights re-laid out [k][rs*512+c]
__device__ float g_xpad[NB * CIN * PADA];                // zero-padded input, [n][c][66][66]
__device__ float g_boxes[NB * NANCH * 4];
__device__ float g_fg[NB * NANCH];
__device__ float g_topbox[NB * PRE_NMS * 4];
__device__ unsigned long long g_mask[NB * PRE_NMS * 32]; // suppression bitmask

// packed f32x2 FMA: both halves are independent IEEE fp32 FMAs (bitwise == fmaf per lane)
__device__ __forceinline__ void ffma2(unsigned long long& d, unsigned long long a, unsigned long long b) {
    asm("fma.rn.f32x2 %0, %1, %2, %0;" : "+l"(d) : "l"(a), "l"(b));
}
__device__ __forceinline__ float f2lo(unsigned long long v) { return __uint_as_float((unsigned)(v & 0xFFFFFFFFull)); }
__device__ __forceinline__ float f2hi(unsigned long long v) { return __uint_as_float((unsigned)(v >> 32)); }

// base anchors (ymin,xmin,ymax,xmax), order: ratio-major, scale-minor (matches reference)
__constant__ float c_ba[9][4] = {
    { -37.254833995939045f,  -82.50966799187809f,   53.254833995939045f,  98.50966799187809f },
    { -82.50966799187809f,  -173.01933598375618f,   98.50966799187809f,  189.01933598375618f },
    { -173.01933598375618f, -354.03867196751236f,  189.01933598375618f,  370.03867196751236f },
    { -56.f,  -56.f,   72.f,   72.f },
    { -120.f, -120.f,  136.f,  136.f },
    { -248.f, -248.f,  264.f,  264.f },
    { -82.50966799187809f,   -37.254833995939045f,  98.50966799187809f,   53.254833995939045f },
    { -173.01933598375618f,  -82.50966799187809f,  189.01933598375618f,   98.50966799187809f },
    { -354.03867196751236f, -173.01933598375618f,  370.03867196751236f,  189.01933598375618f },
};

// ---------------- weight transpose: OIHW [k][c*9+rs] -> [k][rs*512+c] ----------------
__global__ void wtrans_kernel(const float* __restrict__ W) {
    int gid = blockIdx.x * blockDim.x + threadIdx.x;
    if (gid >= COUT * KKtot) return;
    int k  = gid / KKtot;
    int t  = gid - k * KKtot;
    int rs = t >> 9;          // 0..8
    int c  = t & 511;
    g_wt[gid] = W[(size_t)k * KKtot + c * 9 + rs];
}

// ---------------- input halo padding: X[n][c][64][64] -> g_xpad[n][c][66][66] ----------------
__global__ void xpad_kernel(const float* __restrict__ X) {
    int plane = blockIdx.y;                      // 0..4095  (n*512 + c)
    int e = blockIdx.x * blockDim.x + threadIdx.x;
    if (e >= PADA) return;
    int iy = e / PADW, ix = e - iy * PADW;
    float v = 0.f;
    if (iy >= 1 && iy <= 64 && ix >= 1 && ix <= 64)
        v = X[((size_t)plane << 12) + ((iy - 1) << 6) + (ix - 1)];
    g_xpad[(size_t)plane * PADA + e] = v;
}

// ---------------- conv1: 3x3 512->512 + bias + ReLU (implicit im2col SGEMM, FFMA2) ----------------
// Round-6 configuration (proven best; ~95-100% of FFMA2 RF-bank-limited roofline). Frozen.
__global__ __launch_bounds__(256, 2)
void conv1_kernel(const float* __restrict__ Bias) {
    __shared__ float2 As2[2][DEPTH][128];   // weights duplicated {a,a}   32KB
    __shared__ float  Bs[2][DEPTH][128];    //                            16KB

    int bk  = blockIdx.x;           // 0..3    (out-channel tile)
    int bm  = blockIdx.y;           // 0..255  (m tile)
    int tid = threadIdx.x;
    int tx  = tid & 15, ty = tid >> 4;

    unsigned long long acc2[8][4];
#pragma unroll
    for (int i = 0; i < 8; i++)
#pragma unroll
        for (int p = 0; p < 4; p++) acc2[i][p] = 0ull;

    int a_i  = tid >> 1;            // 0..127
    int a_k8 = (tid & 1) * 8;       // 0 or 8
    const float* wrow = g_wt + (size_t)(bk * 128 + a_i) * KKtot + a_k8;
    int m0 = bm * 128;

    // per-thread fixed gather bases (element e: idx = tid + 256e, e=0..7)
    int e_kk[8], e_j[8];
    int base_e[8];
#pragma unroll
    for (int e = 0; e < 8; e++) {
        int idx = tid + 256 * e;
        e_kk[e] = idx >> 7;         // 0..15
        e_j[e]  = idx & 127;
        int m   = m0 + e_j[e];
        int n   = m >> 12;
        int p   = m & 4095;
        int yy  = p >> 6, xx = p & 63;
        base_e[e] = (n * CIN + e_kk[e]) * PADA + (yy + 1) * PADW + (xx + 1);
    }

    float4 av0, av1;
    float  bv[8];

    // prefetch stage 0 (rs=0 => dy=-1,dx=-1 => delta = -67; cb=0)
    av0 = *reinterpret_cast<const float4*>(wrow);
    av1 = *reinterpret_cast<const float4*>(wrow + 4);
#pragma unroll
    for (int e = 0; e < 8; e++) bv[e] = g_xpad[base_e[e] - 67];

#pragma unroll
    for (int q = 0; q < 4; q++) {
        float a = (&av0.x)[q];
        As2[0][a_k8 + q][a_i] = make_float2(a, a);
    }
#pragma unroll
    for (int q = 0; q < 4; q++) {
        float a = (&av1.x)[q];
        As2[0][a_k8 + 4 + q][a_i] = make_float2(a, a);
    }
#pragma unroll
    for (int e = 0; e < 8; e++) Bs[0][e_kk[e]][e_j[e]] = bv[e];
    __syncthreads();

    for (int st = 0; st < NSTEP; st++) {
        int cur = st & 1;
        int stn = st + 1;
        bool havenext = stn < NSTEP;

        // prefetch next stage into registers (hidden under the FMA loop)
        if (havenext) {
            av0 = *reinterpret_cast<const float4*>(wrow + stn * DEPTH);
            av1 = *reinterpret_cast<const float4*>(wrow + stn * DEPTH + 4);
            int rs = stn >> 5, cb = stn & 31;
            int r  = rs / 3, s = rs - 3 * r;
            int c_off = (r - 1) * PADW + (s - 1) + cb * CBSTRIDE;
#pragma unroll
            for (int e = 0; e < 8; e++) bv[e] = g_xpad[base_e[e] + c_off];
        }

        // FMA on current buffer
#pragma unroll
        for (int kk = 0; kk < DEPTH; kk++) {
            ulonglong2 aq0 = *reinterpret_cast<const ulonglong2*>(&As2[cur][kk][ty * 8 + 0]);
            ulonglong2 aq1 = *reinterpret_cast<const ulonglong2*>(&As2[cur][kk][ty * 8 + 2]);
            ulonglong2 aq2 = *reinterpret_cast<const ulonglong2*>(&As2[cur][kk][ty * 8 + 4]);
            ulonglong2 aq3 = *reinterpret_cast<const ulonglong2*>(&As2[cur][kk][ty * 8 + 6]);
            ulonglong2 bq0 = *reinterpret_cast<const ulonglong2*>(&Bs[cur][kk][tx * 4]);
            ulonglong2 bq1 = *reinterpret_cast<const ulonglong2*>(&Bs[cur][kk][tx * 4 + 64]);
            unsigned long long a2[8] = { aq0.x, aq0.y, aq1.x, aq1.y, aq2.x, aq2.y, aq3.x, aq3.y };
            unsigned long long b2[4] = { bq0.x, bq0.y, bq1.x, bq1.y };
#pragma unroll
            for (int i = 0; i < 8; i++)
#pragma unroll
                for (int p = 0; p < 4; p++)
                    ffma2(acc2[i][p], a2[i], b2[p]);
        }

        // store prefetched stage into the other buffer
        if (havenext) {
            int nb = stn & 1;
#pragma unroll
            for (int q = 0; q < 4; q++) {
                float a = (&av0.x)[q];
                As2[nb][a_k8 + q][a_i] = make_float2(a, a);
            }
#pragma unroll
            for (int q = 0; q < 4; q++) {
                float a = (&av1.x)[q];
                As2[nb][a_k8 + 4 + q][a_i] = make_float2(a, a);
            }
#pragma unroll
            for (int e = 0; e < 8; e++) Bs[nb][e_kk[e]][e_j[e]] = bv[e];
        }
        __syncthreads();
    }

    // epilogue: bias + ReLU, write to g_h[k][m] as float4
#pragma unroll
    for (int i = 0; i < 8; i++) {
        int ko = bk * 128 + ty * 8 + i;
        float bias = Bias[ko];
#pragma unroll
        for (int h = 0; h < 2; h++) {
            float4 v;
            v.x = fmaxf(f2lo(acc2[i][h * 2 + 0]) + bias, 0.f);
            v.y = fmaxf(f2hi(acc2[i][h * 2 + 0]) + bias, 0.f);
            v.z = fmaxf(f2lo(acc2[i][h * 2 + 1]) + bias, 0.f);
            v.w = fmaxf(f2hi(acc2[i][h * 2 + 1]) + bias, 0.f);
            *reinterpret_cast<float4*>(&g_h[(size_t)ko * Mtot + m0 + tx * 4 + h * 64]) = v;
        }
    }
}

// ---------------- 1x1 convs: 54 channels, FFMA2, 512 threads/block for 2x occupancy ----------------
// 512 blocks x 512 threads. ty in 0..15 owns 4 channels (gch = ty*4+ch; gch>=54 are dummies).
// tx owns 2 adjacent columns (even/odd pair -> same f32x2 pairing; chains strict ascending-c
// -> bitwise identical to all prior passing rounds).
__global__ __launch_bounds__(512)
void conv1x1_kernel(const float* __restrict__ LW, const float* __restrict__ LB,
                    const float* __restrict__ SW, const float* __restrict__ SB,
                    float* __restrict__ out) {
    __shared__ float2 ws2[64][64];       // duplicated weights {w,w}, 32KB
    int tid = threadIdx.x;
    int tx  = tid & 31, ty = tid >> 5;   // ty 0..15
    int m0  = blockIdx.x * 64;           // 64 columns per block

    unsigned long long acc2[4];
#pragma unroll
    for (int ch = 0; ch < 4; ch++) acc2[ch] = 0ull;

    for (int c0 = 0; c0 < CIN; c0 += 64) {
        __syncthreads();
        for (int t = tid; t < 64 * 64; t += 512) {
            int ch = t >> 6, cc = t & 63;
            float w = 0.f;
            if (ch < 36)      w = LW[ch * CIN + c0 + cc];
            else if (ch < 54) w = SW[(ch - 36) * CIN + c0 + cc];
            ws2[ch][cc] = make_float2(w, w);
        }
        __syncthreads();
        for (int cc = 0; cc < 64; cc++) {
            unsigned long long hv = *reinterpret_cast<const unsigned long long*>(
                &g_h[(size_t)(c0 + cc) * Mtot + m0 + tx * 2]);
#pragma unroll
            for (int ch = 0; ch < 4; ch++) {
                unsigned long long w2 = *reinterpret_cast<const unsigned long long*>(
                    &ws2[ty * 4 + ch][cc]);
                ffma2(acc2[ch], w2, hv);
            }
        }
    }

#pragma unroll
    for (int ch = 0; ch < 4; ch++) {
        int gch = ty * 4 + ch;
        if (gch >= 54) continue;
#pragma unroll
        for (int e = 0; e < 2; e++) {
            int m = m0 + tx * 2 + e;
            int n = m >> 12, p = m & 4095;
            float v = e ? f2hi(acc2[ch]) : f2lo(acc2[ch]);
            if (gch < 36) {
                int an = gch >> 2, j = gch & 3;
                out[OFF_LOCS + ((size_t)n * NANCH + p * 9 + an) * 4 + j] = v + LB[gch];
            } else {
                int sch = gch - 36;
                int an = sch >> 1, j = sch & 1;
                out[OFF_SCORES + ((size_t)n * NANCH + p * 9 + an) * 2 + j] = v + SB[sch];
            }
        }
    }
}

// ---------------- decode + clip + size filter ----------------
__global__ void decode_kernel(const float* __restrict__ out,
                              const int* __restrict__ ihp, const int* __restrict__ iwp) {
    int gid = blockIdx.x * blockDim.x + threadIdx.x;
    if (gid >= NB * NANCH) return;
    int i = gid % NANCH;
    int a = i % 9;
    int p = i / 9;
    float sy = (float)((p >> 6) * 16);
    float sx = (float)((p & 63) * 16);
    float ay0 = sy + c_ba[a][0], ax0 = sx + c_ba[a][1];
    float ay1 = sy + c_ba[a][2], ax1 = sx + c_ba[a][3];
    float ah = ay1 - ay0, aw = ax1 - ax0;
    float acy = ay0 + 0.5f * ah, acx = ax0 + 0.5f * aw;

    float4 l = *(const float4*)&out[OFF_LOCS + (size_t)gid * 4];
    float cy = l.x * ah + acy;
    float cx = l.y * aw + acx;
    float hh = expf(l.z) * ah;
    float ww = expf(l.w) * aw;

    int vih = *ihp, viw = *iwp;
    float Hc = (vih > 0 && vih < 65536) ? (float)vih : __int_as_float(vih);
    float Wc = (viw > 0 && viw < 65536) ? (float)viw : __int_as_float(viw);

    float y0 = fminf(fmaxf(cy - 0.5f * hh, 0.f), Hc);
    float x0 = fminf(fmaxf(cx - 0.5f * ww, 0.f), Wc);
    float y1 = fminf(fmaxf(cy + 0.5f * hh, 0.f), Hc);
    float x1 = fminf(fmaxf(cx + 0.5f * ww, 0.f), Wc);

    *(float4*)&g_boxes[(size_t)gid * 4] = make_float4(y0, x0, y1, x1);
    float sc = out[OFF_SCORES + (size_t)gid * 2 + 1];
    g_fg[gid] = ((y1 - y0) >= 16.f && (x1 - x0) >= 16.f) ? sc : -INFINITY;
}

// ---------------- per-image exact top-2000 (radix select + bitonic sort) ----------------
__device__ __forceinline__ unsigned int fkey(float f) {
    unsigned int b = __float_as_uint(f);
    return (b & 0x80000000u) ? ~b : (b | 0x80000000u);
}

__global__ __launch_bounds__(1024)
void topk_kernel() {
    int n = blockIdx.x;
    const float* fg = g_fg + (size_t)n * NANCH;
    __shared__ unsigned int hist[256];
    __shared__ unsigned int sPref;
    __shared__ int sK, sCnt;
    __shared__ unsigned long long keys[4096];
    int tid = threadIdx.x;

    unsigned int pref = 0; int k = PRE_NMS;
    for (int pass = 0; pass < 4; pass++) {
        int shift = 24 - pass * 8;
        if (tid < 256) hist[tid] = 0u;
        __syncthreads();
        unsigned int mhi = pass ? (0xFFFFFFFFu << (shift + 8)) : 0u;
        for (int i = tid; i < NANCH; i += 1024) {
            unsigned int u = fkey(fg[i]);
            if ((u & mhi) == pref) atomicAdd(&hist[(u >> shift) & 255u], 1u);
        }
        __syncthreads();
        if (tid == 0) {
            int acc = 0, b = 255;
            for (; b > 0; b--) {
                if (acc + (int)hist[b] >= k) break;
                acc += (int)hist[b];
            }
            sPref = pref | ((unsigned)b << shift);
            sK = k - acc;
        }
        __syncthreads();
        pref = sPref; k = sK;
        __syncthreads();
    }
    unsigned int T = pref;
    if (tid == 0) sCnt = 0;
    __syncthreads();
    for (int i = tid; i < NANCH; i += 1024) {
        unsigned int u = fkey(fg[i]);
        if (u >= T) {
            int pos = atomicAdd(&sCnt, 1);
            if (pos < 4096)
                keys[pos] = ((unsigned long long)u << 32) | (unsigned)(0xFFFFFFFFu - (unsigned)i);
        }
    }
    __syncthreads();
    int cnt = sCnt < 4096 ? sCnt : 4096;
    for (int i = cnt + tid; i < 4096; i += 1024) keys[i] = 0ull;

    // bitonic sort, descending (ties: smaller original index first via ~i in low bits)
    for (int size = 2; size <= 4096; size <<= 1) {
        for (int stride = size >> 1; stride > 0; stride >>= 1) {
            __syncthreads();
            for (int t = tid; t < 2048; t += 1024) {
                int i = ((t & ~(stride - 1)) << 1) | (t & (stride - 1));
                int j = i | stride;
                unsigned long long ki = keys[i], kj = keys[j];
                bool descBlock = (i & size) == 0;
                if (descBlock ? (ki < kj) : (ki > kj)) { keys[i] = kj; keys[j] = ki; }
            }
        }
    }
    __syncthreads();

    for (int t = tid; t < PRE_NMS; t += 1024) {
        int idx = (int)(0xFFFFFFFFu - (unsigned int)(keys[t] & 0xFFFFFFFFull));
        float4 b4 = *(const float4*)&g_boxes[((size_t)n * NANCH + idx) * 4];
        *(float4*)&g_topbox[((size_t)n * PRE_NMS + t) * 4] = b4;
    }
}

// ---------------- pairwise IoU suppression bitmask ----------------
__global__ __launch_bounds__(64)
void iou_mask_kernel() {
    int n = blockIdx.z, rb = blockIdx.y, cb = blockIdx.x;
    int t = threadIdx.x;

    // whole block strictly lower-triangle (every col <= every row) -> all-zero mask words
    if (cb < rb) {
        int row = rb * 64 + t;
        if (row < PRE_NMS) g_mask[((size_t)n * PRE_NMS + row) * 32 + cb] = 0ull;
        return;
    }

    __shared__ float4 cbox[64];
    int col0 = cb * 64;
    cbox[t] = (col0 + t < PRE_NMS)
                  ? *(const float4*)&g_topbox[((size_t)n * PRE_NMS + col0 + t) * 4]
                  : make_float4(0, 0, 0, 0);
    __syncthreads();

    int row = rb * 64 + t;
    if (row >= PRE_NMS) return;
    float4 r4 = *(const float4*)&g_topbox[((size_t)n * PRE_NMS + row) * 4];
    float areaR = (r4.z - r4.x) * (r4.w - r4.y);
    unsigned long long bits = 0ull;
    int cmax = min(64, PRE_NMS - col0);
    for (int c = 0; c < cmax; c++) {
        int col = col0 + c;
        if (col <= row) continue;
        float4 c4 = cbox[c];
        float areaC = (c4.z - c4.x) * (c4.w - c4.y);
        float tly = fmaxf(r4.x, c4.x), tlx = fmaxf(r4.y, c4.y);
        float bry = fminf(r4.z, c4.z), brx = fminf(r4.w, c4.w);
        float ih = fmaxf(bry - tly, 0.f), iw = fmaxf(brx - tlx, 0.f);
        float inter = ih * iw;
        float iou = inter / (areaR + areaC - inter + 1e-9f);
        if (iou > 0.7f) bits |= (1ull << c);
    }
    g_mask[((size_t)n * PRE_NMS + row) * 32 + cb] = bits;
}

// ---------------- serial NMS scan (register rem + shfl + deep prefetch) ----------------
#define NMS_PF 25            // prefetch depth; 2000 = 25 * 80
__global__ __launch_bounds__(32)
void nms_scan_kernel(float* __restrict__ out) {
    int n = blockIdx.x;
    int lane = threadIdx.x;
    const unsigned long long* M = g_mask + (size_t)n * PRE_NMS * 32;

    __shared__ int keep[POST_NMS];
    unsigned long long rem = 0ull;     // this lane's 64-column suppression chunk
    int cnt = 0;                        // replicated across lanes

    unsigned long long pre[NMS_PF];
#pragma unroll
    for (int u = 0; u < NMS_PF; u++) pre[u] = M[(size_t)u * 32 + lane];

    for (int base = 0; base < PRE_NMS; base += NMS_PF) {
#pragma unroll
        for (int u = 0; u < NMS_PF; u++) {
            int i = base + u;
            unsigned long long mrow = pre[u];
            int nx = i + NMS_PF;
            if (nx < PRE_NMS) pre[u] = M[(size_t)nx * 32 + lane];
            unsigned long long word = __shfl_sync(0xFFFFFFFFu, rem, i >> 6);
            bool sup = (word >> (i & 63)) & 1ull;
            if (!sup) {
                rem |= mrow;
                if (lane == 0 && cnt < POST_NMS) keep[cnt] = i;
                cnt++;
            }
        }
    }
    __syncwarp();
    int c = cnt < POST_NMS ? cnt : POST_NMS;

    for (int k = lane; k < POST_NMS; k += 32) {
        float4 b = make_float4(0, 0, 0, 0);
        if (k < c) b = *(const float4*)&g_topbox[((size_t)n * PRE_NMS + keep[k]) * 4];
        *(float4*)&out[OFF_ROIS + ((size_t)n * POST_NMS + k) * 4] = b;
        out[OFF_IDX + (size_t)n * POST_NMS + k] = (float)n;
    }
}

// ---------------- launch ----------------
extern "C" void kernel_launch(void* const* d_in, const int* in_sizes, int n_in,
                              void* d_out, int out_size) {
    const float* x   = (const float*)d_in[0];
    const float* c1w = (const float*)d_in[1];
    const float* c1b = (const float*)d_in[2];
    const float* sw  = (const float*)d_in[3];
    const float* sb  = (const float*)d_in[4];
    const float* lw  = (const float*)d_in[5];
    const float* lb  = (const float*)d_in[6];
    const int*   ih  = (const int*)d_in[7];
    const int*   iw  = (const int*)d_in[8];
    float* out = (float*)d_out;

    wtrans_kernel<<<(COUT * KKtot + 255) / 256, 256>>>(c1w);
    xpad_kernel<<<dim3((PADA + 255) / 256, NB * CIN), 256>>>(x);
    conv1_kernel<<<dim3(4, 256), 256>>>(c1b);
    conv1x1_kernel<<<512, 512>>>(lw, lb, sw, sb, out);
    decode_kernel<<<(NB * NANCH + 255) / 256, 256>>>(out, ih, iw);
    topk_kernel<<<NB, 1024>>>();
    iou_mask_kernel<<<dim3(32, 32, NB), 64>>>();
    nms_scan_kernel<<<NB, 32>>>(out);
}

// round 16
// speedup vs baseline: 1.0176x; 1.0106x over previous
#include <cuda_runtime.h>
#include <stdint.h>
#include <math.h>

#define CIN    512
#define COUT   512
#define NB     8
#define HW     4096          // 64*64
#define Mtot   32768         // NB*HW
#define KKtot  4608          // CIN*9
#define NANCH  36864         // HW*9
#define PRE_NMS  2000
#define POST_NMS 300
#define DEPTH  16
#define NSTEP  288           // 9 taps * 32 c-blocks of depth 16
#define PADW   66
#define PADA   4356          // 66*66
#define CBSTRIDE 69696       // 16 channels * 4356 floats per c-block in g_xpad

#define OFF_LOCS   0
#define OFF_SCORES 1179648
#define OFF_ROIS   1769472
#define OFF_IDX    1779072

// ---------------- scratch (device globals; no allocs allowed) ----------------
__device__ float g_h[COUT * Mtot];                       // conv1 output, [cout][m]
__device__ float g_wt[COUT * KKtot];                     // weights re-laid out [k][rs*512+c]
__device__ float g_xpad[NB * CIN * PADA];                // zero-padded input, [n][c][66][66]
__device__ float g_boxes[NB * NANCH * 4];
__device__ float g_fg[NB * NANCH];
__device__ float g_topbox[NB * PRE_NMS * 4];
__device__ unsigned long long g_mask[NB * PRE_NMS * 32]; // suppression bitmask

// packed f32x2 FMA: both halves are independent IEEE fp32 FMAs (bitwise == fmaf per lane)
__device__ __forceinline__ void ffma2(unsigned long long& d, unsigned long long a, unsigned long long b) {
    asm("fma.rn.f32x2 %0, %1, %2, %0;" : "+l"(d) : "l"(a), "l"(b));
}
__device__ __forceinline__ float f2lo(unsigned long long v) { return __uint_as_float((unsigned)(v & 0xFFFFFFFFull)); }
__device__ __forceinline__ float f2hi(unsigned long long v) { return __uint_as_float((unsigned)(v >> 32)); }

// base anchors (ymin,xmin,ymax,xmax), order: ratio-major, scale-minor (matches reference)
__constant__ float c_ba[9][4] = {
    { -37.254833995939045f,  -82.50966799187809f,   53.254833995939045f,  98.50966799187809f },
    { -82.50966799187809f,  -173.01933598375618f,   98.50966799187809f,  189.01933598375618f },
    { -173.01933598375618f, -354.03867196751236f,  189.01933598375618f,  370.03867196751236f },
    { -56.f,  -56.f,   72.f,   72.f },
    { -120.f, -120.f,  136.f,  136.f },
    { -248.f, -248.f,  264.f,  264.f },
    { -82.50966799187809f,   -37.254833995939045f,  98.50966799187809f,   53.254833995939045f },
    { -173.01933598375618f,  -82.50966799187809f,  189.01933598375618f,   98.50966799187809f },
    { -354.03867196751236f, -173.01933598375618f,  370.03867196751236f,  189.01933598375618f },
};

// ---------------- weight transpose: OIHW [k][c*9+rs] -> [k][rs*512+c] ----------------
__global__ void wtrans_kernel(const float* __restrict__ W) {
    int gid = blockIdx.x * blockDim.x + threadIdx.x;
    if (gid >= COUT * KKtot) return;
    int k  = gid / KKtot;
    int t  = gid - k * KKtot;
    int rs = t >> 9;          // 0..8
    int c  = t & 511;
    g_wt[gid] = W[(size_t)k * KKtot + c * 9 + rs];
}

// ---------------- input halo padding: X[n][c][64][64] -> g_xpad[n][c][66][66] ----------------
__global__ void xpad_kernel(const float* __restrict__ X) {
    int plane = blockIdx.y;                      // 0..4095  (n*512 + c)
    int e = blockIdx.x * blockDim.x + threadIdx.x;
    if (e >= PADA) return;
    int iy = e / PADW, ix = e - iy * PADW;
    float v = 0.f;
    if (iy >= 1 && iy <= 64 && ix >= 1 && ix <= 64)
        v = X[((size_t)plane << 12) + ((iy - 1) << 6) + (ix - 1)];
    g_xpad[(size_t)plane * PADA + e] = v;
}

// ---------------- conv1: 3x3 512->512 + bias + ReLU (implicit im2col SGEMM, FFMA2) ----------------
// Round-6 configuration (proven best; ~95-100% of FFMA2 RF-bank-limited roofline). Frozen.
__global__ __launch_bounds__(256, 2)
void conv1_kernel(const float* __restrict__ Bias) {
    __shared__ float2 As2[2][DEPTH][128];   // weights duplicated {a,a}   32KB
    __shared__ float  Bs[2][DEPTH][128];    //                            16KB

    int bk  = blockIdx.x;           // 0..3    (out-channel tile)
    int bm  = blockIdx.y;           // 0..255  (m tile)
    int tid = threadIdx.x;
    int tx  = tid & 15, ty = tid >> 4;

    unsigned long long acc2[8][4];
#pragma unroll
    for (int i = 0; i < 8; i++)
#pragma unroll
        for (int p = 0; p < 4; p++) acc2[i][p] = 0ull;

    int a_i  = tid >> 1;            // 0..127
    int a_k8 = (tid & 1) * 8;       // 0 or 8
    const float* wrow = g_wt + (size_t)(bk * 128 + a_i) * KKtot + a_k8;
    int m0 = bm * 128;

    // per-thread fixed gather bases (element e: idx = tid + 256e, e=0..7)
    int e_kk[8], e_j[8];
    int base_e[8];
#pragma unroll
    for (int e = 0; e < 8; e++) {
        int idx = tid + 256 * e;
        e_kk[e] = idx >> 7;         // 0..15
        e_j[e]  = idx & 127;
        int m   = m0 + e_j[e];
        int n   = m >> 12;
        int p   = m & 4095;
        int yy  = p >> 6, xx = p & 63;
        base_e[e] = (n * CIN + e_kk[e]) * PADA + (yy + 1) * PADW + (xx + 1);
    }

    float4 av0, av1;
    float  bv[8];

    // prefetch stage 0 (rs=0 => dy=-1,dx=-1 => delta = -67; cb=0)
    av0 = *reinterpret_cast<const float4*>(wrow);
    av1 = *reinterpret_cast<const float4*>(wrow + 4);
#pragma unroll
    for (int e = 0; e < 8; e++) bv[e] = g_xpad[base_e[e] - 67];

#pragma unroll
    for (int q = 0; q < 4; q++) {
        float a = (&av0.x)[q];
        As2[0][a_k8 + q][a_i] = make_float2(a, a);
    }
#pragma unroll
    for (int q = 0; q < 4; q++) {
        float a = (&av1.x)[q];
        As2[0][a_k8 + 4 + q][a_i] = make_float2(a, a);
    }
#pragma unroll
    for (int e = 0; e < 8; e++) Bs[0][e_kk[e]][e_j[e]] = bv[e];
    __syncthreads();

    for (int st = 0; st < NSTEP; st++) {
        int cur = st & 1;
        int stn = st + 1;
        bool havenext = stn < NSTEP;

        // prefetch next stage into registers (hidden under the FMA loop)
        if (havenext) {
            av0 = *reinterpret_cast<const float4*>(wrow + stn * DEPTH);
            av1 = *reinterpret_cast<const float4*>(wrow + stn * DEPTH + 4);
            int rs = stn >> 5, cb = stn & 31;
            int r  = rs / 3, s = rs - 3 * r;
            int c_off = (r - 1) * PADW + (s - 1) + cb * CBSTRIDE;
#pragma unroll
            for (int e = 0; e < 8; e++) bv[e] = g_xpad[base_e[e] + c_off];
        }

        // FMA on current buffer
#pragma unroll
        for (int kk = 0; kk < DEPTH; kk++) {
            ulonglong2 aq0 = *reinterpret_cast<const ulonglong2*>(&As2[cur][kk][ty * 8 + 0]);
            ulonglong2 aq1 = *reinterpret_cast<const ulonglong2*>(&As2[cur][kk][ty * 8 + 2]);
            ulonglong2 aq2 = *reinterpret_cast<const ulonglong2*>(&As2[cur][kk][ty * 8 + 4]);
            ulonglong2 aq3 = *reinterpret_cast<const ulonglong2*>(&As2[cur][kk][ty * 8 + 6]);
            ulonglong2 bq0 = *reinterpret_cast<const ulonglong2*>(&Bs[cur][kk][tx * 4]);
            ulonglong2 bq1 = *reinterpret_cast<const ulonglong2*>(&Bs[cur][kk][tx * 4 + 64]);
            unsigned long long a2[8] = { aq0.x, aq0.y, aq1.x, aq1.y, aq2.x, aq2.y, aq3.x, aq3.y };
            unsigned long long b2[4] = { bq0.x, bq0.y, bq1.x, bq1.y };
#pragma unroll
            for (int i = 0; i < 8; i++)
#pragma unroll
                for (int p = 0; p < 4; p++)
                    ffma2(acc2[i][p], a2[i], b2[p]);
        }

        // store prefetched stage into the other buffer
        if (havenext) {
            int nb = stn & 1;
#pragma unroll
            for (int q = 0; q < 4; q++) {
                float a = (&av0.x)[q];
                As2[nb][a_k8 + q][a_i] = make_float2(a, a);
            }
#pragma unroll
            for (int q = 0; q < 4; q++) {
                float a = (&av1.x)[q];
                As2[nb][a_k8 + 4 + q][a_i] = make_float2(a, a);
            }
#pragma unroll
            for (int e = 0; e < 8; e++) Bs[nb][e_kk[e]][e_j[e]] = bv[e];
        }
        __syncthreads();
    }

    // epilogue: bias + ReLU, write to g_h[k][m] as float4
#pragma unroll
    for (int i = 0; i < 8; i++) {
        int ko = bk * 128 + ty * 8 + i;
        float bias = Bias[ko];
#pragma unroll
        for (int h = 0; h < 2; h++) {
            float4 v;
            v.x = fmaxf(f2lo(acc2[i][h * 2 + 0]) + bias, 0.f);
            v.y = fmaxf(f2hi(acc2[i][h * 2 + 0]) + bias, 0.f);
            v.z = fmaxf(f2lo(acc2[i][h * 2 + 1]) + bias, 0.f);
            v.w = fmaxf(f2hi(acc2[i][h * 2 + 1]) + bias, 0.f);
            *reinterpret_cast<float4*>(&g_h[(size_t)ko * Mtot + m0 + tx * 4 + h * 64]) = v;
        }
    }
}

// ---------------- 1x1 convs: round-6 proven version (frozen). 512 blocks x 256 threads. ----------------
// ty 0..7 owns 7 channels; tx owns 2 adjacent columns (even/odd pair, chains ascending-c).
__global__ __launch_bounds__(256)
void conv1x1_kernel(const float* __restrict__ LW, const float* __restrict__ LB,
                    const float* __restrict__ SW, const float* __restrict__ SB,
                    float* __restrict__ out) {
    __shared__ float2 ws2[56][64];       // duplicated weights {w,w}, 28KB
    int tid = threadIdx.x;
    int tx  = tid & 31, ty = tid >> 5;   // ty 0..7
    int m0  = blockIdx.x * 64;           // 64 columns per block

    unsigned long long acc2[7];
#pragma unroll
    for (int ch = 0; ch < 7; ch++) acc2[ch] = 0ull;

    for (int c0 = 0; c0 < CIN; c0 += 64) {
        __syncthreads();
        for (int t = tid; t < 56 * 64; t += 256) {
            int ch = t >> 6, cc = t & 63;
            float w = 0.f;
            if (ch < 36)      w = LW[ch * CIN + c0 + cc];
            else if (ch < 54) w = SW[(ch - 36) * CIN + c0 + cc];
            ws2[ch][cc] = make_float2(w, w);
        }
        __syncthreads();
        for (int cc = 0; cc < 64; cc++) {
            unsigned long long hv = *reinterpret_cast<const unsigned long long*>(
                &g_h[(size_t)(c0 + cc) * Mtot + m0 + tx * 2]);
#pragma unroll
            for (int ch = 0; ch < 7; ch++) {
                unsigned long long w2 = *reinterpret_cast<const unsigned long long*>(
                    &ws2[ty * 7 + ch][cc]);
                ffma2(acc2[ch], w2, hv);
            }
        }
    }

#pragma unroll
    for (int ch = 0; ch < 7; ch++) {
        int gch = ty * 7 + ch;
        if (gch >= 54) continue;
#pragma unroll
        for (int e = 0; e < 2; e++) {
            int m = m0 + tx * 2 + e;
            int n = m >> 12, p = m & 4095;
            float v = e ? f2hi(acc2[ch]) : f2lo(acc2[ch]);
            if (gch < 36) {
                int an = gch >> 2, j = gch & 3;
                out[OFF_LOCS + ((size_t)n * NANCH + p * 9 + an) * 4 + j] = v + LB[gch];
            } else {
                int sch = gch - 36;
                int an = sch >> 1, j = sch & 1;
                out[OFF_SCORES + ((size_t)n * NANCH + p * 9 + an) * 2 + j] = v + SB[sch];
            }
        }
    }
}

// ---------------- decode + clip + size filter ----------------
__global__ void decode_kernel(const float* __restrict__ out,
                              const int* __restrict__ ihp, const int* __restrict__ iwp) {
    int gid = blockIdx.x * blockDim.x + threadIdx.x;
    if (gid >= NB * NANCH) return;
    int i = gid % NANCH;
    int a = i % 9;
    int p = i / 9;
    float sy = (float)((p >> 6) * 16);
    float sx = (float)((p & 63) * 16);
    float ay0 = sy + c_ba[a][0], ax0 = sx + c_ba[a][1];
    float ay1 = sy + c_ba[a][2], ax1 = sx + c_ba[a][3];
    float ah = ay1 - ay0, aw = ax1 - ax0;
    float acy = ay0 + 0.5f * ah, acx = ax0 + 0.5f * aw;

    float4 l = *(const float4*)&out[OFF_LOCS + (size_t)gid * 4];
    float cy = l.x * ah + acy;
    float cx = l.y * aw + acx;
    float hh = expf(l.z) * ah;
    float ww = expf(l.w) * aw;

    int vih = *ihp, viw = *iwp;
    float Hc = (vih > 0 && vih < 65536) ? (float)vih : __int_as_float(vih);
    float Wc = (viw > 0 && viw < 65536) ? (float)viw : __int_as_float(viw);

    float y0 = fminf(fmaxf(cy - 0.5f * hh, 0.f), Hc);
    float x0 = fminf(fmaxf(cx - 0.5f * ww, 0.f), Wc);
    float y1 = fminf(fmaxf(cy + 0.5f * hh, 0.f), Hc);
    float x1 = fminf(fmaxf(cx + 0.5f * ww, 0.f), Wc);

    *(float4*)&g_boxes[(size_t)gid * 4] = make_float4(y0, x0, y1, x1);
    float sc = out[OFF_SCORES + (size_t)gid * 2 + 1];
    g_fg[gid] = ((y1 - y0) >= 16.f && (x1 - x0) >= 16.f) ? sc : -INFINITY;
}

// ---------------- per-image exact top-2000 (radix select + bitonic sort) ----------------
__device__ __forceinline__ unsigned int fkey(float f) {
    unsigned int b = __float_as_uint(f);
    return (b & 0x80000000u) ? ~b : (b | 0x80000000u);
}

__global__ __launch_bounds__(1024)
void topk_kernel() {
    int n = blockIdx.x;
    const float* fg = g_fg + (size_t)n * NANCH;
    __shared__ unsigned int hist[256];
    __shared__ unsigned int sPref;
    __shared__ int sK, sCnt;
    __shared__ unsigned long long keys[4096];
    int tid = threadIdx.x;

    unsigned int pref = 0; int k = PRE_NMS;
    for (int pass = 0; pass < 4; pass++) {
        int shift = 24 - pass * 8;
        if (tid < 256) hist[tid] = 0u;
        __syncthreads();
        unsigned int mhi = pass ? (0xFFFFFFFFu << (shift + 8)) : 0u;
        for (int i = tid; i < NANCH; i += 1024) {
            unsigned int u = fkey(fg[i]);
            if ((u & mhi) == pref) atomicAdd(&hist[(u >> shift) & 255u], 1u);
        }
        __syncthreads();
        if (tid == 0) {
            int acc = 0, b = 255;
            for (; b > 0; b--) {
                if (acc + (int)hist[b] >= k) break;
                acc += (int)hist[b];
            }
            sPref = pref | ((unsigned)b << shift);
            sK = k - acc;
        }
        __syncthreads();
        pref = sPref; k = sK;
        __syncthreads();
    }
    unsigned int T = pref;
    if (tid == 0) sCnt = 0;
    __syncthreads();
    for (int i = tid; i < NANCH; i += 1024) {
        unsigned int u = fkey(fg[i]);
        if (u >= T) {
            int pos = atomicAdd(&sCnt, 1);
            if (pos < 4096)
                keys[pos] = ((unsigned long long)u << 32) | (unsigned)(0xFFFFFFFFu - (unsigned)i);
        }
    }
    __syncthreads();
    int cnt = sCnt < 4096 ? sCnt : 4096;
    for (int i = cnt + tid; i < 4096; i += 1024) keys[i] = 0ull;

    // bitonic sort, descending (ties: smaller original index first via ~i in low bits)
    for (int size = 2; size <= 4096; size <<= 1) {
        for (int stride = size >> 1; stride > 0; stride >>= 1) {
            __syncthreads();
            for (int t = tid; t < 2048; t += 1024) {
                int i = ((t & ~(stride - 1)) << 1) | (t & (stride - 1));
                int j = i | stride;
                unsigned long long ki = keys[i], kj = keys[j];
                bool descBlock = (i & size) == 0;
                if (descBlock ? (ki < kj) : (ki > kj)) { keys[i] = kj; keys[j] = ki; }
            }
        }
    }
    __syncthreads();

    for (int t = tid; t < PRE_NMS; t += 1024) {
        int idx = (int)(0xFFFFFFFFu - (unsigned int)(keys[t] & 0xFFFFFFFFull));
        float4 b4 = *(const float4*)&g_boxes[((size_t)n * NANCH + idx) * 4];
        *(float4*)&g_topbox[((size_t)n * PRE_NMS + t) * 4] = b4;
    }
}

// ---------------- pairwise IoU suppression bitmask ----------------
__global__ __launch_bounds__(64)
void iou_mask_kernel() {
    int n = blockIdx.z, rb = blockIdx.y, cb = blockIdx.x;
    int t = threadIdx.x;

    // whole block strictly lower-triangle (every col <= every row) -> all-zero mask words
    if (cb < rb) {
        int row = rb * 64 + t;
        if (row < PRE_NMS) g_mask[((size_t)n * PRE_NMS + row) * 32 + cb] = 0ull;
        return;
    }

    __shared__ float4 cbox[64];
    int col0 = cb * 64;
    cbox[t] = (col0 + t < PRE_NMS)
                  ? *(const float4*)&g_topbox[((size_t)n * PRE_NMS + col0 + t) * 4]
                  : make_float4(0, 0, 0, 0);
    __syncthreads();

    int row = rb * 64 + t;
    if (row >= PRE_NMS) return;
    float4 r4 = *(const float4*)&g_topbox[((size_t)n * PRE_NMS + row) * 4];
    float areaR = (r4.z - r4.x) * (r4.w - r4.y);
    unsigned long long bits = 0ull;
    int cmax = min(64, PRE_NMS - col0);
    for (int c = 0; c < cmax; c++) {
        int col = col0 + c;
        if (col <= row) continue;
        float4 c4 = cbox[c];
        float areaC = (c4.z - c4.x) * (c4.w - c4.y);
        float tly = fmaxf(r4.x, c4.x), tlx = fmaxf(r4.y, c4.y);
        float bry = fminf(r4.z, c4.z), brx = fminf(r4.w, c4.w);
        float ih = fmaxf(bry - tly, 0.f), iw = fmaxf(brx - tlx, 0.f);
        float inter = ih * iw;
        float iou = inter / (areaR + areaC - inter + 1e-9f);
        if (iou > 0.7f) bits |= (1ull << c);
    }
    g_mask[((size_t)n * PRE_NMS + row) * 32 + cb] = bits;
}

// ---------------- serial NMS scan (register rem + shfl + deep prefetch) ----------------
#define NMS_PF 25            // prefetch depth; 2000 = 25 * 80
__global__ __launch_bounds__(32)
void nms_scan_kernel(float* __restrict__ out) {
    int n = blockIdx.x;
    int lane = threadIdx.x;
    const unsigned long long* M = g_mask + (size_t)n * PRE_NMS * 32;

    __shared__ int keep[POST_NMS];
    unsigned long long rem = 0ull;     // this lane's 64-column suppression chunk
    int cnt = 0;                        // replicated across lanes

    unsigned long long pre[NMS_PF];
#pragma unroll
    for (int u = 0; u < NMS_PF; u++) pre[u] = M[(size_t)u * 32 + lane];

    for (int base = 0; base < PRE_NMS; base += NMS_PF) {
#pragma unroll
        for (int u = 0; u < NMS_PF; u++) {
            int i = base + u;
            unsigned long long mrow = pre[u];
            int nx = i + NMS_PF;
            if (nx < PRE_NMS) pre[u] = M[(size_t)nx * 32 + lane];
            unsigned long long word = __shfl_sync(0xFFFFFFFFu, rem, i >> 6);
            bool sup = (word >> (i & 63)) & 1ull;
            if (!sup) {
                rem |= mrow;
                if (lane == 0 && cnt < POST_NMS) keep[cnt] = i;
                cnt++;
            }
        }
    }
    __syncwarp();
    int c = cnt < POST_NMS ? cnt : POST_NMS;

    for (int k = lane; k < POST_NMS; k += 32) {
        float4 b = make_float4(0, 0, 0, 0);
        if (k < c) b = *(const float4*)&g_topbox[((size_t)n * PRE_NMS + keep[k]) * 4];
        *(float4*)&out[OFF_ROIS + ((size_t)n * POST_NMS + k) * 4] = b;
        out[OFF_IDX + (size_t)n * POST_NMS + k] = (float)n;
    }
}

// ---------------- launch ----------------
extern "C" void kernel_launch(void* const* d_in, const int* in_sizes, int n_in,
                              void* d_out, int out_size) {
    const float* x   = (const float*)d_in[0];
    const float* c1w = (const float*)d_in[1];
    const float* c1b = (const float*)d_in[2];
    const float* sw  = (const float*)d_in[3];
    const float* sb  = (const float*)d_in[4];
    const float* lw  = (const float*)d_in[5];
    const float* lb  = (const float*)d_in[6];
    const int*   ih  = (const int*)d_in[7];
    const int*   iw  = (const int*)d_in[8];
    float* out = (float*)d_out;

    wtrans_kernel<<<(COUT * KKtot + 255) / 256, 256>>>(c1w);
    xpad_kernel<<<dim3((PADA + 255) / 256, NB * CIN), 256>>>(x);
    conv1_kernel<<<dim3(4, 256), 256>>>(c1b);
    conv1x1_kernel<<<512, 256>>>(lw, lb, sw, sb, out);
    decode_kernel<<<(NB * NANCH + 255) / 256, 256>>>(out, ih, iw);
    topk_kernel<<<NB, 1024>>>();
    iou_mask_kernel<<<dim3(32, 32, NB), 64>>>();
    nms_scan_kernel<<<NB, 32>>>(out);
}

// round 17
// speedup vs baseline: 1.0247x; 1.0069x over previous
#include <cuda_runtime.h>
#include <stdint.h>
#include <math.h>

#define CIN    512
#define COUT   512
#define NB     8
#define HW     4096          // 64*64
#define Mtot   32768         // NB*HW
#define KKtot  4608          // CIN*9
#define NANCH  36864         // HW*9
#define PRE_NMS  2000
#define POST_NMS 300
#define DEPTH  16
#define NSTEP  288           // 9 taps * 32 c-blocks of depth 16
#define PADW   66
#define PADA   4356          // 66*66
#define CBSTRIDE 69696       // 16 channels * 4356 floats per c-block in g_xpad

#define OFF_LOCS   0
#define OFF_SCORES 1179648
#define OFF_ROIS   1769472
#define OFF_IDX    1779072

// ---------------- scratch (device globals; no allocs allowed) ----------------
__device__ float g_h[COUT * Mtot];                       // conv1 output, [cout][m]
__device__ float g_wt[COUT * KKtot];                     // weights re-laid out [k][rs*512+c]
__device__ float g_xpad[NB * CIN * PADA];                // zero-padded input, [n][c][66][66]
__device__ float g_boxes[NB * NANCH * 4];
__device__ float g_fg[NB * NANCH];
__device__ float g_topbox[NB * PRE_NMS * 4];
__device__ unsigned long long g_mask[NB * PRE_NMS * 32]; // suppression bitmask

// packed f32x2 FMA: both halves are independent IEEE fp32 FMAs (bitwise == fmaf per lane)
__device__ __forceinline__ void ffma2(unsigned long long& d, unsigned long long a, unsigned long long b) {
    asm("fma.rn.f32x2 %0, %1, %2, %0;" : "+l"(d) : "l"(a), "l"(b));
}
__device__ __forceinline__ float f2lo(unsigned long long v) { return __uint_as_float((unsigned)(v & 0xFFFFFFFFull)); }
__device__ __forceinline__ float f2hi(unsigned long long v) { return __uint_as_float((unsigned)(v >> 32)); }

// base anchors (ymin,xmin,ymax,xmax), order: ratio-major, scale-minor (matches reference)
__constant__ float c_ba[9][4] = {
    { -37.254833995939045f,  -82.50966799187809f,   53.254833995939045f,  98.50966799187809f },
    { -82.50966799187809f,  -173.01933598375618f,   98.50966799187809f,  189.01933598375618f },
    { -173.01933598375618f, -354.03867196751236f,  189.01933598375618f,  370.03867196751236f },
    { -56.f,  -56.f,   72.f,   72.f },
    { -120.f, -120.f,  136.f,  136.f },
    { -248.f, -248.f,  264.f,  264.f },
    { -82.50966799187809f,   -37.254833995939045f,  98.50966799187809f,   53.254833995939045f },
    { -173.01933598375618f,  -82.50966799187809f,  189.01933598375618f,   98.50966799187809f },
    { -354.03867196751236f, -173.01933598375618f,  370.03867196751236f,  189.01933598375618f },
};

// ---------------- weight transpose: OIHW [k][c*9+rs] -> [k][rs*512+c] ----------------
__global__ void wtrans_kernel(const float* __restrict__ W) {
    int gid = blockIdx.x * blockDim.x + threadIdx.x;
    if (gid >= COUT * KKtot) return;
    int k  = gid / KKtot;
    int t  = gid - k * KKtot;
    int rs = t >> 9;          // 0..8
    int c  = t & 511;
    g_wt[gid] = W[(size_t)k * KKtot + c * 9 + rs];
}

// ---------------- input halo padding: X[n][c][64][64] -> g_xpad[n][c][66][66] ----------------
__global__ void xpad_kernel(const float* __restrict__ X) {
    int plane = blockIdx.y;                      // 0..4095  (n*512 + c)
    int e = blockIdx.x * blockDim.x + threadIdx.x;
    if (e >= PADA) return;
    int iy = e / PADW, ix = e - iy * PADW;
    float v = 0.f;
    if (iy >= 1 && iy <= 64 && ix >= 1 && ix <= 64)
        v = X[((size_t)plane << 12) + ((iy - 1) << 6) + (ix - 1)];
    g_xpad[(size_t)plane * PADA + e] = v;
}

// ---------------- conv1: 3x3 512->512 + bias + ReLU (implicit im2col SGEMM, FFMA2) ----------------
// Round-6 configuration (proven best; ~95-100% of FFMA2 RF-bank-limited roofline). Frozen.
__global__ __launch_bounds__(256, 2)
void conv1_kernel(const float* __restrict__ Bias) {
    __shared__ float2 As2[2][DEPTH][128];   // weights duplicated {a,a}   32KB
    __shared__ float  Bs[2][DEPTH][128];    //                            16KB

    int bk  = blockIdx.x;           // 0..3    (out-channel tile)
    int bm  = blockIdx.y;           // 0..255  (m tile)
    int tid = threadIdx.x;
    int tx  = tid & 15, ty = tid >> 4;

    unsigned long long acc2[8][4];
#pragma unroll
    for (int i = 0; i < 8; i++)
#pragma unroll
        for (int p = 0; p < 4; p++) acc2[i][p] = 0ull;

    int a_i  = tid >> 1;            // 0..127
    int a_k8 = (tid & 1) * 8;       // 0 or 8
    const float* wrow = g_wt + (size_t)(bk * 128 + a_i) * KKtot + a_k8;
    int m0 = bm * 128;

    // per-thread fixed gather bases (element e: idx = tid + 256e, e=0..7)
    int e_kk[8], e_j[8];
    int base_e[8];
#pragma unroll
    for (int e = 0; e < 8; e++) {
        int idx = tid + 256 * e;
        e_kk[e] = idx >> 7;         // 0..15
        e_j[e]  = idx & 127;
        int m   = m0 + e_j[e];
        int n   = m >> 12;
        int p   = m & 4095;
        int yy  = p >> 6, xx = p & 63;
        base_e[e] = (n * CIN + e_kk[e]) * PADA + (yy + 1) * PADW + (xx + 1);
    }

    float4 av0, av1;
    float  bv[8];

    // prefetch stage 0 (rs=0 => dy=-1,dx=-1 => delta = -67; cb=0)
    av0 = *reinterpret_cast<const float4*>(wrow);
    av1 = *reinterpret_cast<const float4*>(wrow + 4);
#pragma unroll
    for (int e = 0; e < 8; e++) bv[e] = g_xpad[base_e[e] - 67];

#pragma unroll
    for (int q = 0; q < 4; q++) {
        float a = (&av0.x)[q];
        As2[0][a_k8 + q][a_i] = make_float2(a, a);
    }
#pragma unroll
    for (int q = 0; q < 4; q++) {
        float a = (&av1.x)[q];
        As2[0][a_k8 + 4 + q][a_i] = make_float2(a, a);
    }
#pragma unroll
    for (int e = 0; e < 8; e++) Bs[0][e_kk[e]][e_j[e]] = bv[e];
    __syncthreads();

    for (int st = 0; st < NSTEP; st++) {
        int cur = st & 1;
        int stn = st + 1;
        bool havenext = stn < NSTEP;

        // prefetch next stage into registers (hidden under the FMA loop)
        if (havenext) {
            av0 = *reinterpret_cast<const float4*>(wrow + stn * DEPTH);
            av1 = *reinterpret_cast<const float4*>(wrow + stn * DEPTH + 4);
            int rs = stn >> 5, cb = stn & 31;
            int r  = rs / 3, s = rs - 3 * r;
            int c_off = (r - 1) * PADW + (s - 1) + cb * CBSTRIDE;
#pragma unroll
            for (int e = 0; e < 8; e++) bv[e] = g_xpad[base_e[e] + c_off];
        }

        // FMA on current buffer
#pragma unroll
        for (int kk = 0; kk < DEPTH; kk++) {
            ulonglong2 aq0 = *reinterpret_cast<const ulonglong2*>(&As2[cur][kk][ty * 8 + 0]);
            ulonglong2 aq1 = *reinterpret_cast<const ulonglong2*>(&As2[cur][kk][ty * 8 + 2]);
            ulonglong2 aq2 = *reinterpret_cast<const ulonglong2*>(&As2[cur][kk][ty * 8 + 4]);
            ulonglong2 aq3 = *reinterpret_cast<const ulonglong2*>(&As2[cur][kk][ty * 8 + 6]);
            ulonglong2 bq0 = *reinterpret_cast<const ulonglong2*>(&Bs[cur][kk][tx * 4]);
            ulonglong2 bq1 = *reinterpret_cast<const ulonglong2*>(&Bs[cur][kk][tx * 4 + 64]);
            unsigned long long a2[8] = { aq0.x, aq0.y, aq1.x, aq1.y, aq2.x, aq2.y, aq3.x, aq3.y };
            unsigned long long b2[4] = { bq0.x, bq0.y, bq1.x, bq1.y };
#pragma unroll
            for (int i = 0; i < 8; i++)
#pragma unroll
                for (int p = 0; p < 4; p++)
                    ffma2(acc2[i][p], a2[i], b2[p]);
        }

        // store prefetched stage into the other buffer
        if (havenext) {
            int nb = stn & 1;
#pragma unroll
            for (int q = 0; q < 4; q++) {
                float a = (&av0.x)[q];
                As2[nb][a_k8 + q][a_i] = make_float2(a, a);
            }
#pragma unroll
            for (int q = 0; q < 4; q++) {
                float a = (&av1.x)[q];
                As2[nb][a_k8 + 4 + q][a_i] = make_float2(a, a);
            }
#pragma unroll
            for (int e = 0; e < 8; e++) Bs[nb][e_kk[e]][e_j[e]] = bv[e];
        }
        __syncthreads();
    }

    // epilogue: bias + ReLU, write to g_h[k][m] as float4
#pragma unroll
    for (int i = 0; i < 8; i++) {
        int ko = bk * 128 + ty * 8 + i;
        float bias = Bias[ko];
#pragma unroll
        for (int h = 0; h < 2; h++) {
            float4 v;
            v.x = fmaxf(f2lo(acc2[i][h * 2 + 0]) + bias, 0.f);
            v.y = fmaxf(f2hi(acc2[i][h * 2 + 0]) + bias, 0.f);
            v.z = fmaxf(f2lo(acc2[i][h * 2 + 1]) + bias, 0.f);
            v.w = fmaxf(f2hi(acc2[i][h * 2 + 1]) + bias, 0.f);
            *reinterpret_cast<float4*>(&g_h[(size_t)ko * Mtot + m0 + tx * 4 + h * 64]) = v;
        }
    }
}

// ---------------- 1x1 convs: 54 channels, FFMA2, 4 cols/thread + 512-thread blocks ----------------
// 256 blocks x 512 threads (16 warps -> ~27 warps/SM at 1.7 CTA/SM).
// ty 0..13 owns 4 channels (gch = ty*4+ch; 54,55 zero-weight dummies); ty 14,15 barrier-only.
// tx owns cols {4tx..4tx+3} = two even/odd-adjacent f32x2 pairs; chains strict ascending-c
// -> bitwise identical accumulation to all prior passing rounds.
__global__ __launch_bounds__(512)
void conv1x1_kernel(const float* __restrict__ LW, const float* __restrict__ LB,
                    const float* __restrict__ SW, const float* __restrict__ SB,
                    float* __restrict__ out) {
    __shared__ float2 ws2[56][64];       // duplicated weights {w,w}, 28KB
    int tid = threadIdx.x;
    int tx  = tid & 31, ty = tid >> 5;   // ty 0..15
    int m0  = blockIdx.x * 128;          // 128 columns per block

    unsigned long long acc2[4][2];
#pragma unroll
    for (int ch = 0; ch < 4; ch++) { acc2[ch][0] = 0ull; acc2[ch][1] = 0ull; }

    const float* hbase = &g_h[m0 + tx * 4];
    bool active = (ty < 14);

    for (int c0 = 0; c0 < CIN; c0 += 64) {
        __syncthreads();
        for (int t = tid; t < 56 * 64; t += 512) {
            int ch = t >> 6, cc = t & 63;
            float w = 0.f;
            if (ch < 36)      w = LW[ch * CIN + c0 + cc];
            else if (ch < 54) w = SW[(ch - 36) * CIN + c0 + cc];
            ws2[ch][cc] = make_float2(w, w);
        }
        __syncthreads();
        if (active) {
            for (int cc = 0; cc < 64; cc++) {
                ulonglong2 hq = *reinterpret_cast<const ulonglong2*>(
                    hbase + (size_t)(c0 + cc) * Mtot);
#pragma unroll
                for (int ch = 0; ch < 4; ch++) {
                    unsigned long long w2 = *reinterpret_cast<const unsigned long long*>(
                        &ws2[ty * 4 + ch][cc]);
                    ffma2(acc2[ch][0], w2, hq.x);
                    ffma2(acc2[ch][1], w2, hq.y);
                }
            }
        }
    }

    if (active) {
#pragma unroll
        for (int ch = 0; ch < 4; ch++) {
            int gch = ty * 4 + ch;
            if (gch >= 54) continue;
#pragma unroll
            for (int e = 0; e < 4; e++) {
                int m = m0 + tx * 4 + e;
                int n = m >> 12, p = m & 4095;
                unsigned long long a = acc2[ch][e >> 1];
                float v = (e & 1) ? f2hi(a) : f2lo(a);
                if (gch < 36) {
                    int an = gch >> 2, j = gch & 3;
                    out[OFF_LOCS + ((size_t)n * NANCH + p * 9 + an) * 4 + j] = v + LB[gch];
                } else {
                    int sch = gch - 36;
                    int an = sch >> 1, j = sch & 1;
                    out[OFF_SCORES + ((size_t)n * NANCH + p * 9 + an) * 2 + j] = v + SB[sch];
                }
            }
        }
    }
}

// ---------------- decode + clip + size filter ----------------
__global__ void decode_kernel(const float* __restrict__ out,
                              const int* __restrict__ ihp, const int* __restrict__ iwp) {
    int gid = blockIdx.x * blockDim.x + threadIdx.x;
    if (gid >= NB * NANCH) return;
    int i = gid % NANCH;
    int a = i % 9;
    int p = i / 9;
    float sy = (float)((p >> 6) * 16);
    float sx = (float)((p & 63) * 16);
    float ay0 = sy + c_ba[a][0], ax0 = sx + c_ba[a][1];
    float ay1 = sy + c_ba[a][2], ax1 = sx + c_ba[a][3];
    float ah = ay1 - ay0, aw = ax1 - ax0;
    float acy = ay0 + 0.5f * ah, acx = ax0 + 0.5f * aw;

    float4 l = *(const float4*)&out[OFF_LOCS + (size_t)gid * 4];
    float cy = l.x * ah + acy;
    float cx = l.y * aw + acx;
    float hh = expf(l.z) * ah;
    float ww = expf(l.w) * aw;

    int vih = *ihp, viw = *iwp;
    float Hc = (vih > 0 && vih < 65536) ? (float)vih : __int_as_float(vih);
    float Wc = (viw > 0 && viw < 65536) ? (float)viw : __int_as_float(viw);

    float y0 = fminf(fmaxf(cy - 0.5f * hh, 0.f), Hc);
    float x0 = fminf(fmaxf(cx - 0.5f * ww, 0.f), Wc);
    float y1 = fminf(fmaxf(cy + 0.5f * hh, 0.f), Hc);
    float x1 = fminf(fmaxf(cx + 0.5f * ww, 0.f), Wc);

    *(float4*)&g_boxes[(size_t)gid * 4] = make_float4(y0, x0, y1, x1);
    float sc = out[OFF_SCORES + (size_t)gid * 2 + 1];
    g_fg[gid] = ((y1 - y0) >= 16.f && (x1 - x0) >= 16.f) ? sc : -INFINITY;
}

// ---------------- per-image exact top-2000 (radix select + bitonic sort) ----------------
__device__ __forceinline__ unsigned int fkey(float f) {
    unsigned int b = __float_as_uint(f);
    return (b & 0x80000000u) ? ~b : (b | 0x80000000u);
}

__global__ __launch_bounds__(1024)
void topk_kernel() {
    int n = blockIdx.x;
    const float* fg = g_fg + (size_t)n * NANCH;
    __shared__ unsigned int hist[256];
    __shared__ unsigned int sPref;
    __shared__ int sK, sCnt;
    __shared__ unsigned long long keys[4096];
    int tid = threadIdx.x;

    unsigned int pref = 0; int k = PRE_NMS;
    for (int pass = 0; pass < 4; pass++) {
        int shift = 24 - pass * 8;
        if (tid < 256) hist[tid] = 0u;
        __syncthreads();
        unsigned int mhi = pass ? (0xFFFFFFFFu << (shift + 8)) : 0u;
        for (int i = tid; i < NANCH; i += 1024) {
            unsigned int u = fkey(fg[i]);
            if ((u & mhi) == pref) atomicAdd(&hist[(u >> shift) & 255u], 1u);
        }
        __syncthreads();
        if (tid == 0) {
            int acc = 0, b = 255;
            for (; b > 0; b--) {
                if (acc + (int)hist[b] >= k) break;
                acc += (int)hist[b];
            }
            sPref = pref | ((unsigned)b << shift);
            sK = k - acc;
        }
        __syncthreads();
        pref = sPref; k = sK;
        __syncthreads();
    }
    unsigned int T = pref;
    if (tid == 0) sCnt = 0;
    __syncthreads();
    for (int i = tid; i < NANCH; i += 1024) {
        unsigned int u = fkey(fg[i]);
        if (u >= T) {
            int pos = atomicAdd(&sCnt, 1);
            if (pos < 4096)
                keys[pos] = ((unsigned long long)u << 32) | (unsigned)(0xFFFFFFFFu - (unsigned)i);
        }
    }
    __syncthreads();
    int cnt = sCnt < 4096 ? sCnt : 4096;
    for (int i = cnt + tid; i < 4096; i += 1024) keys[i] = 0ull;

    // bitonic sort, descending (ties: smaller original index first via ~i in low bits)
    for (int size = 2; size <= 4096; size <<= 1) {
        for (int stride = size >> 1; stride > 0; stride >>= 1) {
            __syncthreads();
            for (int t = tid; t < 2048; t += 1024) {
                int i = ((t & ~(stride - 1)) << 1) | (t & (stride - 1));
                int j = i | stride;
                unsigned long long ki = keys[i], kj = keys[j];
                bool descBlock = (i & size) == 0;
                if (descBlock ? (ki < kj) : (ki > kj)) { keys[i] = kj; keys[j] = ki; }
            }
        }
    }
    __syncthreads();

    for (int t = tid; t < PRE_NMS; t += 1024) {
        int idx = (int)(0xFFFFFFFFu - (unsigned int)(keys[t] & 0xFFFFFFFFull));
        float4 b4 = *(const float4*)&g_boxes[((size_t)n * NANCH + idx) * 4];
        *(float4*)&g_topbox[((size_t)n * PRE_NMS + t) * 4] = b4;
    }
}

// ---------------- pairwise IoU suppression bitmask ----------------
__global__ __launch_bounds__(64)
void iou_mask_kernel() {
    int n = blockIdx.z, rb = blockIdx.y, cb = blockIdx.x;
    int t = threadIdx.x;

    // whole block strictly lower-triangle (every col <= every row) -> all-zero mask words
    if (cb < rb) {
        int row = rb * 64 + t;
        if (row < PRE_NMS) g_mask[((size_t)n * PRE_NMS + row) * 32 + cb] = 0ull;
        return;
    }

    __shared__ float4 cbox[64];
    int col0 = cb * 64;
    cbox[t] = (col0 + t < PRE_NMS)
                  ? *(const float4*)&g_topbox[((size_t)n * PRE_NMS + col0 + t) * 4]
                  : make_float4(0, 0, 0, 0);
    __syncthreads();

    int row = rb * 64 + t;
    if (row >= PRE_NMS) return;
    float4 r4 = *(const float4*)&g_topbox[((size_t)n * PRE_NMS + row) * 4];
    float areaR = (r4.z - r4.x) * (r4.w - r4.y);
    unsigned long long bits = 0ull;
    int cmax = min(64, PRE_NMS - col0);
    for (int c = 0; c < cmax; c++) {
        int col = col0 + c;
        if (col <= row) continue;
        float4 c4 = cbox[c];
        float areaC = (c4.z - c4.x) * (c4.w - c4.y);
        float tly = fmaxf(r4.x, c4.x), tlx = fmaxf(r4.y, c4.y);
        float bry = fminf(r4.z, c4.z), brx = fminf(r4.w, c4.w);
        float ih = fmaxf(bry - tly, 0.f), iw = fmaxf(brx - tlx, 0.f);
        float inter = ih * iw;
        float iou = inter / (areaR + areaC - inter + 1e-9f);
        if (iou > 0.7f) bits |= (1ull << c);
    }
    g_mask[((size_t)n * PRE_NMS + row) * 32 + cb] = bits;
}

// ---------------- serial NMS scan (register rem + shfl + deep prefetch) ----------------
#define NMS_PF 25            // prefetch depth; 2000 = 25 * 80
__global__ __launch_bounds__(32)
void nms_scan_kernel(float* __restrict__ out) {
    int n = blockIdx.x;
    int lane = threadIdx.x;
    const unsigned long long* M = g_mask + (size_t)n * PRE_NMS * 32;

    __shared__ int keep[POST_NMS];
    unsigned long long rem = 0ull;     // this lane's 64-column suppression chunk
    int cnt = 0;                        // replicated across lanes

    unsigned long long pre[NMS_PF];
#pragma unroll
    for (int u = 0; u < NMS_PF; u++) pre[u] = M[(size_t)u * 32 + lane];

    for (int base = 0; base < PRE_NMS; base += NMS_PF) {
#pragma unroll
        for (int u = 0; u < NMS_PF; u++) {
            int i = base + u;
            unsigned long long mrow = pre[u];
            int nx = i + NMS_PF;
            if (nx < PRE_NMS) pre[u] = M[(size_t)nx * 32 + lane];
            unsigned long long word = __shfl_sync(0xFFFFFFFFu, rem, i >> 6);
            bool sup = (word >> (i & 63)) & 1ull;
            if (!sup) {
                rem |= mrow;
                if (lane == 0 && cnt < POST_NMS) keep[cnt] = i;
                cnt++;
            }
        }
    }
    __syncwarp();
    int c = cnt < POST_NMS ? cnt : POST_NMS;

    for (int k = lane; k < POST_NMS; k += 32) {
        float4 b = make_float4(0, 0, 0, 0);
        if (k < c) b = *(const float4*)&g_topbox[((size_t)n * PRE_NMS + keep[k]) * 4];
        *(float4*)&out[OFF_ROIS + ((size_t)n * POST_NMS + k) * 4] = b;
        out[OFF_IDX + (size_t)n * POST_NMS + k] = (float)n;
    }
}

// ---------------- launch ----------------
extern "C" void kernel_launch(void* const* d_in, const int* in_sizes, int n_in,
                              void* d_out, int out_size) {
    const float* x   = (const float*)d_in[0];
    const float* c1w = (const float*)d_in[1];
    const float* c1b = (const float*)d_in[2];
    const float* sw  = (const float*)d_in[3];
    const float* sb  = (const float*)d_in[4];
    const float* lw  = (const float*)d_in[5];
    const float* lb  = (const float*)d_in[6];
    const int*   ih  = (const int*)d_in[7];
    const int*   iw  = (const int*)d_in[8];
    float* out = (float*)d_out;

    wtrans_kernel<<<(COUT * KKtot + 255) / 256, 256>>>(c1w);
    xpad_kernel<<<dim3((PADA + 255) / 256, NB * CIN), 256>>>(x);
    conv1_kernel<<<dim3(4, 256), 256>>>(c1b);
    conv1x1_kernel<<<256, 512>>>(lw, lb, sw, sb, out);
    decode_kernel<<<(NB * NANCH + 255) / 256, 256>>>(out, ih, iw);
    topk_kernel<<<NB, 1024>>>();
    iou_mask_kernel<<<dim3(32, 32, NB), 64>>>();
    nms_scan_kernel<<<NB, 32>>>(out);
}